// round 9
// baseline (speedup 1.0000x reference)
#include <cuda_runtime.h>
#include <cuda_bf16.h>
#include <cstdint>
#include <cstddef>

#define S_  1024
#define P_  1024
#define J_  2048
#define B_  4
#define E_  1024
#define H_  16
#define I_  64
#define HI_ 1024

// ---------------- fp32 scratch ----------------------------------------------
__device__ float g_q[(size_t)S_ * B_ * HI_];          // (S,B,H*I)
__device__ float g_kv[(size_t)J_ * B_ * 2 * HI_];     // (J,B,2*H*I)  keys | values
__device__ float g_p[(size_t)J_ * HI_];               // (J,H*I)
__device__ float g_sc[(size_t)B_ * H_ * S_ * J_];     // (B*H, S, J) logits -> probs
__device__ float g_awv[(size_t)S_ * B_ * HI_];        // (S,B,H*I)
__device__ float g_o[(size_t)S_ * B_ * E_];           // pre-LN output

// ---------------- bf16-split scratch ----------------------------------------
__device__ __nv_bfloat16 g_xhi[(size_t)8192 * 1024];   // [memory ; inputMHA]
__device__ __nv_bfloat16 g_xlo[(size_t)8192 * 1024];
__device__ __nv_bfloat16 g_pehi[(size_t)2048 * 1024];  // posEmb
__device__ __nv_bfloat16 g_pelo[(size_t)2048 * 1024];
__device__ __nv_bfloat16 g_ahi[(size_t)4096 * 1024];   // awv
__device__ __nv_bfloat16 g_alo[(size_t)4096 * 1024];
__device__ __nv_bfloat16 g_wqhi[(size_t)1024 * 1024];  // W^T [N,K]
__device__ __nv_bfloat16 g_wqlo[(size_t)1024 * 1024];
__device__ __nv_bfloat16 g_wkvhi[(size_t)2048 * 1024];
__device__ __nv_bfloat16 g_wkvlo[(size_t)2048 * 1024];
__device__ __nv_bfloat16 g_wphi[(size_t)1024 * 1024];
__device__ __nv_bfloat16 g_wplo[(size_t)1024 * 1024];
__device__ __nv_bfloat16 g_wohi[(size_t)1024 * 1024];
__device__ __nv_bfloat16 g_wolo[(size_t)1024 * 1024];

// ---------------- small helpers ---------------------------------------------
__device__ __forceinline__ uint32_t smem_u32(const void* p) {
    uint32_t a;
    asm("{ .reg .u64 t; cvta.to.shared.u64 t, %1; cvt.u32.u64 %0, t; }"
        : "=r"(a) : "l"(p));
    return a;
}
__device__ __forceinline__ void cpa16(uint32_t s, const void* g) {
    asm volatile("cp.async.cg.shared.global [%0], [%1], 16;" :: "r"(s), "l"(g));
}
__device__ __forceinline__ void ldm_x4(uint32_t* d, uint32_t addr) {
    asm volatile("ldmatrix.sync.aligned.m8n8.x4.shared.b16 {%0,%1,%2,%3}, [%4];"
                 : "=r"(d[0]), "=r"(d[1]), "=r"(d[2]), "=r"(d[3]) : "r"(addr));
}
__device__ __forceinline__ void ldm_x2(uint32_t* d, uint32_t addr) {
    asm volatile("ldmatrix.sync.aligned.m8n8.x2.shared.b16 {%0,%1}, [%2];"
                 : "=r"(d[0]), "=r"(d[1]) : "r"(addr));
}
__device__ __forceinline__ void mma16816(float* c, const uint32_t* a, const uint32_t* b) {
    asm volatile("mma.sync.aligned.m16n8k16.row.col.f32.bf16.bf16.f32 "
                 "{%0,%1,%2,%3},{%4,%5,%6,%7},{%8,%9},{%0,%1,%2,%3};"
                 : "+f"(c[0]), "+f"(c[1]), "+f"(c[2]), "+f"(c[3])
                 : "r"(a[0]), "r"(a[1]), "r"(a[2]), "r"(a[3]), "r"(b[0]), "r"(b[1]));
}

// ---------------- HMMA bf16x3 GEMM: C[M,N] = A[M,K]*B[N,K]^T (+res) ---------
// CTA tile 128x128, 8 warps (warp tile 64x32), K-chunk 32, 3-stage cp.async.
#define ROWB   80          // padded row stride in bytes (32 bf16 + 8 pad)
#define TILEB  (128 * ROWB)  // 10240
#define STG    (4 * TILEB)   // Ahi,Alo,Bhi,Blo per stage = 40960
#define NSTG   3
#define GM_SMEM (NSTG * STG) // 122880

__device__ __forceinline__ void gload(uint32_t dst, const __nv_bfloat16* src,
                                      int row0, int ld, int k0, int tid) {
    // 128 rows x 64 bytes (4 x 16B chunks) -> padded smem
#pragma unroll
    for (int it = 0; it < 2; it++) {
        int idx = it * 256 + tid;
        int r = idx >> 2, c = idx & 3;
        cpa16(dst + r * ROWB + c * 16, src + (size_t)(row0 + r) * ld + k0 + c * 8);
    }
}

__global__ __launch_bounds__(256) void hmma_gemm(const __nv_bfloat16* __restrict__ Ahi,
                                                 const __nv_bfloat16* __restrict__ Alo,
                                                 const __nv_bfloat16* __restrict__ Bhi,
                                                 const __nv_bfloat16* __restrict__ Blo,
                                                 const float* __restrict__ res,
                                                 float* __restrict__ C,
                                                 int M, int N, int K) {
    extern __shared__ char smc[];
    uint32_t sb = smem_u32(smc);
    int tid = threadIdx.x, wid = tid >> 5, lane = tid & 31;
    int wm = wid & 1, wn = wid >> 1;            // warp grid 2 x 4
    int m0 = blockIdx.y * 128, n0 = blockIdx.x * 128;

    float acc[4][4][4];
#pragma unroll
    for (int t = 0; t < 4; t++)
#pragma unroll
        for (int s = 0; s < 4; s++)
#pragma unroll
            for (int r = 0; r < 4; r++) acc[t][s][r] = 0.f;

    const int NC = K / 32;
    // prologue: stages 0,1
#pragma unroll
    for (int st = 0; st < 2; st++) {
        uint32_t base = sb + st * STG;
        gload(base,             Ahi, m0, K, st * 32, tid);
        gload(base + TILEB,     Alo, m0, K, st * 32, tid);
        gload(base + 2 * TILEB, Bhi, n0, K, st * 32, tid);
        gload(base + 3 * TILEB, Blo, n0, K, st * 32, tid);
        asm volatile("cp.async.commit_group;" ::: "memory");
    }

    // per-thread ldmatrix address components
    int a_row = (lane & 15), a_hi16 = (lane >> 4) * 16;
    int b_row = (lane & 7), b_hi16 = ((lane >> 3) & 1) * 16;

    for (int c = 0; c < NC; c++) {
        if (c + 2 < NC) {
            uint32_t base = sb + ((c + 2) % NSTG) * STG;
            gload(base,             Ahi, m0, K, (c + 2) * 32, tid);
            gload(base + TILEB,     Alo, m0, K, (c + 2) * 32, tid);
            gload(base + 2 * TILEB, Bhi, n0, K, (c + 2) * 32, tid);
            gload(base + 3 * TILEB, Blo, n0, K, (c + 2) * 32, tid);
        }
        asm volatile("cp.async.commit_group;" ::: "memory");
        asm volatile("cp.async.wait_group 2;" ::: "memory");
        __syncthreads();

        uint32_t base = sb + (c % NSTG) * STG;
        uint32_t aH = base, aL = base + TILEB, bH = base + 2 * TILEB, bL = base + 3 * TILEB;
#pragma unroll
        for (int kk = 0; kk < 2; kk++) {
            uint32_t ah[4][4], al[4][4], bh[4][2], bl[4][2];
#pragma unroll
            for (int t = 0; t < 4; t++) {
                uint32_t off = (uint32_t)((wm * 64 + t * 16 + a_row) * ROWB + kk * 32 + a_hi16);
                ldm_x4(ah[t], aH + off);
                ldm_x4(al[t], aL + off);
            }
#pragma unroll
            for (int s = 0; s < 4; s++) {
                uint32_t off = (uint32_t)((wn * 32 + s * 8 + b_row) * ROWB + kk * 32 + b_hi16);
                ldm_x2(bh[s], bH + off);
                ldm_x2(bl[s], bL + off);
            }
            // bf16x3 terms issued as 3 independent sweeps over all 16
            // accumulators: same-acc reuse distance = 16 MMAs (hides HMMA
            // latency), instead of back-to-back RAW chains of 3.
#pragma unroll
            for (int t = 0; t < 4; t++)
#pragma unroll
                for (int s = 0; s < 4; s++)
                    mma16816(acc[t][s], ah[t], bh[s]);
#pragma unroll
            for (int t = 0; t < 4; t++)
#pragma unroll
                for (int s = 0; s < 4; s++)
                    mma16816(acc[t][s], ah[t], bl[s]);
#pragma unroll
            for (int t = 0; t < 4; t++)
#pragma unroll
                for (int s = 0; s < 4; s++)
                    mma16816(acc[t][s], al[t], bh[s]);
        }
        __syncthreads();
    }

    // epilogue: D frag mapping m16n8: d0,d1 @ (l>>2, (l&3)*2), d2,d3 @ (+8, same)
#pragma unroll
    for (int t = 0; t < 4; t++) {
        int mg = m0 + wm * 64 + t * 16 + (lane >> 2);
#pragma unroll
        for (int s = 0; s < 4; s++) {
            int ng = n0 + wn * 32 + s * 8 + (lane & 3) * 2;
            float2 v0 = make_float2(acc[t][s][0], acc[t][s][1]);
            float2 v1 = make_float2(acc[t][s][2], acc[t][s][3]);
            if (res) {
                float2 r0 = *(const float2*)&res[(size_t)mg * N + ng];
                float2 r1 = *(const float2*)&res[(size_t)(mg + 8) * N + ng];
                v0.x += r0.x; v0.y += r0.y; v1.x += r1.x; v1.y += r1.y;
            }
            *(float2*)&C[(size_t)mg * N + ng] = v0;
            *(float2*)&C[(size_t)(mg + 8) * N + ng] = v1;
        }
    }
}

// ---------------- fp32 -> bf16 hi/lo split ----------------------------------
__global__ __launch_bounds__(256) void split_kernel(const float* __restrict__ x,
                                                    __nv_bfloat16* __restrict__ hi,
                                                    __nv_bfloat16* __restrict__ lo,
                                                    int n) {
    int i = (blockIdx.x * 256 + threadIdx.x) * 4;
    if (i >= n) return;
    float4 v = *(const float4*)&x[i];
    __nv_bfloat162 h0, h1, l0, l1;
    h0.x = __float2bfloat16(v.x); h0.y = __float2bfloat16(v.y);
    h1.x = __float2bfloat16(v.z); h1.y = __float2bfloat16(v.w);
    l0.x = __float2bfloat16(v.x - __bfloat162float(h0.x));
    l0.y = __float2bfloat16(v.y - __bfloat162float(h0.y));
    l1.x = __float2bfloat16(v.z - __bfloat162float(h1.x));
    l1.y = __float2bfloat16(v.w - __bfloat162float(h1.y));
    *(__nv_bfloat162*)&hi[i] = h0;
    *(__nv_bfloat162*)&hi[i + 2] = h1;
    *(__nv_bfloat162*)&lo[i] = l0;
    *(__nv_bfloat162*)&lo[i + 2] = l1;
}

// ---------------- W[K,N] -> T[N,K] transpose + split ------------------------
__global__ void tsplit_kernel(const float* __restrict__ W,
                              __nv_bfloat16* __restrict__ Thi,
                              __nv_bfloat16* __restrict__ Tlo,
                              int Kd, int Nd) {
    __shared__ float t[32][33];
    int n0 = blockIdx.x * 32, k0 = blockIdx.y * 32;
    int tx = threadIdx.x, ty = threadIdx.y;
#pragma unroll
    for (int r = 0; r < 32; r += 8)
        t[ty + r][tx] = W[(size_t)(k0 + ty + r) * Nd + n0 + tx];
    __syncthreads();
#pragma unroll
    for (int r = 0; r < 32; r += 8) {
        float v = t[tx][ty + r];
        __nv_bfloat16 h = __float2bfloat16(v);
        Thi[(size_t)(n0 + ty + r) * Kd + k0 + tx] = h;
        Tlo[(size_t)(n0 + ty + r) * Kd + k0 + tx] =
            __float2bfloat16(v - __bfloat162float(h));
    }
}

// ---------------- scores: content + rel-shifted position, mask, scale ------
#define SC_SMEM_FLOATS (2 * 64 * 65 + 128 * 65 + 64)
#define SC_SMEM_BYTES  (SC_SMEM_FLOATS * 4)

__global__ __launch_bounds__(256) void scores_kernel(const float* __restrict__ u,
                                                     const float* __restrict__ vvec) {
    int bh = blockIdx.z;
    int b = bh >> 4, h = bh & 15;
    int s0 = blockIdx.y << 6, j0 = blockIdx.x << 6;
    int tid = threadIdx.x;
    float* out = g_sc + ((size_t)bh * S_ + s0) * J_ + j0;

    if (j0 > P_ + s0 + 63) {
        float4 m4 = make_float4(-1e30f, -1e30f, -1e30f, -1e30f);
#pragma unroll
        for (int it = 0; it < 4; it++) {
            int idx = it * 256 + tid;
            int r = idx >> 4, c = (idx & 15) << 2;
            *(float4*)&out[(size_t)r * J_ + c] = m4;
        }
        return;
    }

    extern __shared__ float smf[];
    float* qu_s = smf;
    float* K_s  = smf + 64 * 65;
    float* p_s  = smf + 2 * 64 * 65;
    float* w_s  = smf + 2 * 64 * 65 + 128 * 65;

    if (tid < 64) w_s[tid] = vvec[h * 64 + tid] - u[h * 64 + tid];

#pragma unroll
    for (int it = 0; it < 4; it++) {
        int idx = it * 256 + tid;
        int r = idx >> 4, i4 = (idx & 15) << 2;
        float4 q4 = *(const float4*)&g_q[((size_t)(s0 + r) * B_ + b) * HI_ + h * 64 + i4];
        float4 u4 = *(const float4*)&u[h * 64 + i4];
        qu_s[r * 65 + i4 + 0] = q4.x + u4.x;
        qu_s[r * 65 + i4 + 1] = q4.y + u4.y;
        qu_s[r * 65 + i4 + 2] = q4.z + u4.z;
        qu_s[r * 65 + i4 + 3] = q4.w + u4.w;
        float4 k4 = *(const float4*)&g_kv[((size_t)(j0 + r) * B_ + b) * (2 * HI_) + h * 64 + i4];
        K_s[r * 65 + i4 + 0] = k4.x;
        K_s[r * 65 + i4 + 1] = k4.y;
        K_s[r * 65 + i4 + 2] = k4.z;
        K_s[r * 65 + i4 + 3] = k4.w;
    }
    int d0 = j0 - s0 + 960;
#pragma unroll
    for (int it = 0; it < 8; it++) {
        int idx = it * 256 + tid;
        int r = idx >> 4, i4 = (idx & 15) << 2;
        int d = d0 + r;
        float4 p4 = make_float4(0.f, 0.f, 0.f, 0.f);
        if (d >= 0 && d < J_)
            p4 = *(const float4*)&g_p[(size_t)d * HI_ + h * 64 + i4];
        p_s[r * 65 + i4 + 0] = p4.x;
        p_s[r * 65 + i4 + 1] = p4.y;
        p_s[r * 65 + i4 + 2] = p4.z;
        p_s[r * 65 + i4 + 3] = p4.w;
    }
    __syncthreads();

    int tx = tid & 15, ty = tid >> 4;
    float acc[4][4];
#pragma unroll
    for (int r = 0; r < 4; r++)
#pragma unroll
        for (int c = 0; c < 4; c++) acc[r][c] = 0.f;

    int pb = (tx << 2) - (ty << 2) + 60;

    for (int i = 0; i < 64; i++) {
        float a[4], av[4], k[4], pv[7];
        float w = w_s[i];
#pragma unroll
        for (int r = 0; r < 4; r++) {
            a[r] = qu_s[((ty << 2) + r) * 65 + i];
            av[r] = a[r] + w;
        }
#pragma unroll
        for (int c = 0; c < 4; c++) k[c] = K_s[((tx << 2) + c) * 65 + i];
#pragma unroll
        for (int d = 0; d < 7; d++) pv[d] = p_s[(pb + d) * 65 + i];
#pragma unroll
        for (int r = 0; r < 4; r++)
#pragma unroll
            for (int c = 0; c < 4; c++)
                acc[r][c] = fmaf(a[r], k[c], fmaf(av[r], pv[c - r + 3], acc[r][c]));
    }

#pragma unroll
    for (int r = 0; r < 4; r++) {
        int s = s0 + (ty << 2) + r;
        int jb = j0 + (tx << 2);
        float4 o4;
        float* po = (float*)&o4;
#pragma unroll
        for (int c = 0; c < 4; c++)
            po[c] = (jb + c <= P_ + s) ? acc[r][c] * 0.125f : -1e30f;
        *(float4*)&out[(size_t)((ty << 2) + r) * J_ + (tx << 2)] = o4;
    }
}

// ---------------- row softmax over J=2048 ----------------------------------
__global__ __launch_bounds__(256) void softmax_kernel() {
    float* row = g_sc + ((size_t)blockIdx.y * S_ + blockIdx.x) * J_;
    int tid = threadIdx.x;
    float4 v0 = *(float4*)&row[tid * 8];
    float4 v1 = *(float4*)&row[tid * 8 + 4];
    float m = fmaxf(fmaxf(fmaxf(v0.x, v0.y), fmaxf(v0.z, v0.w)),
                    fmaxf(fmaxf(v1.x, v1.y), fmaxf(v1.z, v1.w)));
    __shared__ float red[8];
#pragma unroll
    for (int o = 16; o > 0; o >>= 1) m = fmaxf(m, __shfl_xor_sync(0xffffffffu, m, o));
    if ((tid & 31) == 0) red[tid >> 5] = m;
    __syncthreads();
    m = red[0];
#pragma unroll
    for (int i = 1; i < 8; i++) m = fmaxf(m, red[i]);

    v0.x = __expf(v0.x - m); v0.y = __expf(v0.y - m);
    v0.z = __expf(v0.z - m); v0.w = __expf(v0.w - m);
    v1.x = __expf(v1.x - m); v1.y = __expf(v1.y - m);
    v1.z = __expf(v1.z - m); v1.w = __expf(v1.w - m);
    float s = v0.x + v0.y + v0.z + v0.w + v1.x + v1.y + v1.z + v1.w;
    __syncthreads();
#pragma unroll
    for (int o = 16; o > 0; o >>= 1) s += __shfl_xor_sync(0xffffffffu, s, o);
    if ((tid & 31) == 0) red[tid >> 5] = s;
    __syncthreads();
    s = 0.f;
#pragma unroll
    for (int i = 0; i < 8; i++) s += red[i];
    float inv = 1.0f / s;
    v0.x *= inv; v0.y *= inv; v0.z *= inv; v0.w *= inv;
    v1.x *= inv; v1.y *= inv; v1.z *= inv; v1.w *= inv;
    *(float4*)&row[tid * 8] = v0;
    *(float4*)&row[tid * 8 + 4] = v1;
}

// ---------------- awv = probs @ V -------------------------------------------
__global__ __launch_bounds__(256) void awv_kernel() {
    int bh = blockIdx.y;
    int b = bh >> 4, h = bh & 15;
    int s0 = blockIdx.x << 7;
    int tid = threadIdx.x;
    int tx = tid & 15, ty = tid >> 4;
    __shared__ float Ps[16 * 132];
    __shared__ float Vs[16 * 68];
    float acc[8][4];
#pragma unroll
    for (int r = 0; r < 8; r++)
#pragma unroll
        for (int c = 0; c < 4; c++) acc[r][c] = 0.f;

    const float* Prow = g_sc + ((size_t)bh * S_ + s0) * J_;
    int kmax = P_ + s0 + 128;

    for (int j0 = 0; j0 < kmax; j0 += 16) {
        __syncthreads();
#pragma unroll
        for (int it = 0; it < 2; it++) {
            int idx = it * 256 + tid;
            int sr = idx >> 2, j4 = (idx & 3) << 2;
            float4 p4 = *(const float4*)&Prow[(size_t)sr * J_ + j0 + j4];
            Ps[(j4 + 0) * 132 + sr] = p4.x;
            Ps[(j4 + 1) * 132 + sr] = p4.y;
            Ps[(j4 + 2) * 132 + sr] = p4.z;
            Ps[(j4 + 3) * 132 + sr] = p4.w;
        }
        {
            int jr = tid >> 4, i4 = (tid & 15) << 2;
            float4 v4 = *(const float4*)&g_kv[((size_t)(j0 + jr) * B_ + b) * (2 * HI_) + HI_ + h * 64 + i4];
            *(float4*)&Vs[jr * 68 + i4] = v4;
        }
        __syncthreads();
#pragma unroll
        for (int jj = 0; jj < 16; jj++) {
            float a[8], bb[4];
            *(float4*)(a)     = *(const float4*)&Ps[jj * 132 + (ty << 3)];
            *(float4*)(a + 4) = *(const float4*)&Ps[jj * 132 + (ty << 3) + 4];
            *(float4*)(bb)    = *(const float4*)&Vs[jj * 68 + (tx << 2)];
#pragma unroll
            for (int r = 0; r < 8; r++)
#pragma unroll
                for (int c = 0; c < 4; c++)
                    acc[r][c] = fmaf(a[r], bb[c], acc[r][c]);
        }
    }
#pragma unroll
    for (int r = 0; r < 8; r++) {
        int s = s0 + (ty << 3) + r;
        float4 o;
        o.x = acc[r][0]; o.y = acc[r][1]; o.z = acc[r][2]; o.w = acc[r][3];
        *(float4*)&g_awv[((size_t)s * B_ + b) * HI_ + h * 64 + (tx << 2)] = o;
    }
}

// ---------------- LayerNorm over E=1024 ------------------------------------
__global__ __launch_bounds__(256) void ln_kernel(const float* __restrict__ gamma,
                                                 const float* __restrict__ beta,
                                                 float* __restrict__ out) {
    int row = blockIdx.x;
    const float* x = g_o + (size_t)row * E_;
    int tid = threadIdx.x;
    float4 v = *(const float4*)&x[tid << 2];
    float s1 = v.x + v.y + v.z + v.w;
    float s2 = v.x * v.x + v.y * v.y + v.z * v.z + v.w * v.w;
    __shared__ float r1[8], r2[8];
#pragma unroll
    for (int o = 16; o > 0; o >>= 1) {
        s1 += __shfl_xor_sync(0xffffffffu, s1, o);
        s2 += __shfl_xor_sync(0xffffffffu, s2, o);
    }
    if ((tid & 31) == 0) { r1[tid >> 5] = s1; r2[tid >> 5] = s2; }
    __syncthreads();
    float S1 = 0.f, S2 = 0.f;
#pragma unroll
    for (int i = 0; i < 8; i++) { S1 += r1[i]; S2 += r2[i]; }
    float mean = S1 * (1.0f / E_);
    float var = S2 * (1.0f / E_) - mean * mean;
    float rstd = rsqrtf(var + 1e-5f);
    float4 g = *(const float4*)&gamma[tid << 2];
    float4 bb = *(const float4*)&beta[tid << 2];
    float4 o;
    o.x = (v.x - mean) * rstd * g.x + bb.x;
    o.y = (v.y - mean) * rstd * g.y + bb.y;
    o.z = (v.z - mean) * rstd * g.z + bb.z;
    o.w = (v.w - mean) * rstd * g.w + bb.w;
    *(float4*)&out[(size_t)row * E_ + (tid << 2)] = o;
}

// ---------------- launch ----------------------------------------------------
extern "C" void kernel_launch(void* const* d_in, const int* in_sizes, int n_in,
                              void* d_out, int out_size) {
    (void)in_sizes; (void)n_in; (void)out_size;
    const float* inputMHA = (const float*)d_in[0];
    const float* posEmb   = (const float*)d_in[1];
    const float* memory   = (const float*)d_in[2];
    const float* u        = (const float*)d_in[3];
    const float* v        = (const float*)d_in[4];
    const float* W_kv     = (const float*)d_in[6];
    const float* W_q      = (const float*)d_in[7];
    const float* W_p      = (const float*)d_in[8];
    const float* W_o      = (const float*)d_in[9];
    const float* gamma    = (const float*)d_in[10];
    const float* beta     = (const float*)d_in[11];

    float *pq, *pkv, *pp, *pawv, *po;
    cudaGetSymbolAddress((void**)&pq, g_q);
    cudaGetSymbolAddress((void**)&pkv, g_kv);
    cudaGetSymbolAddress((void**)&pp, g_p);
    cudaGetSymbolAddress((void**)&pawv, g_awv);
    cudaGetSymbolAddress((void**)&po, g_o);

    __nv_bfloat16 *xhi, *xlo, *pehi, *pelo, *ahi, *alo;
    __nv_bfloat16 *wqh, *wql, *wkh, *wkl, *wph, *wpl, *woh, *wol;
    cudaGetSymbolAddress((void**)&xhi, g_xhi);
    cudaGetSymbolAddress((void**)&xlo, g_xlo);
    cudaGetSymbolAddress((void**)&pehi, g_pehi);
    cudaGetSymbolAddress((void**)&pelo, g_pelo);
    cudaGetSymbolAddress((void**)&ahi, g_ahi);
    cudaGetSymbolAddress((void**)&alo, g_alo);
    cudaGetSymbolAddress((void**)&wqh, g_wqhi);
    cudaGetSymbolAddress((void**)&wql, g_wqlo);
    cudaGetSymbolAddress((void**)&wkh, g_wkvhi);
    cudaGetSymbolAddress((void**)&wkl, g_wkvlo);
    cudaGetSymbolAddress((void**)&wph, g_wphi);
    cudaGetSymbolAddress((void**)&wpl, g_wplo);
    cudaGetSymbolAddress((void**)&woh, g_wohi);
    cudaGetSymbolAddress((void**)&wol, g_wolo);

    cudaFuncSetAttribute(scores_kernel, cudaFuncAttributeMaxDynamicSharedMemorySize,
                         SC_SMEM_BYTES);
    cudaFuncSetAttribute(hmma_gemm, cudaFuncAttributeMaxDynamicSharedMemorySize, GM_SMEM);

    // ---- convert inputs to bf16 hi/lo ----
    split_kernel<<<4096, 256>>>(memory, xhi, xlo, P_ * B_ * E_);
    split_kernel<<<4096, 256>>>(inputMHA, xhi + (size_t)P_ * B_ * E_,
                                xlo + (size_t)P_ * B_ * E_, S_ * B_ * E_);
    split_kernel<<<2048, 256>>>(posEmb, pehi, pelo, J_ * E_);
    tsplit_kernel<<<dim3(HI_ / 32, E_ / 32), dim3(32, 8)>>>(W_q, wqh, wql, E_, HI_);
    tsplit_kernel<<<dim3(2 * HI_ / 32, E_ / 32), dim3(32, 8)>>>(W_kv, wkh, wkl, E_, 2 * HI_);
    tsplit_kernel<<<dim3(HI_ / 32, E_ / 32), dim3(32, 8)>>>(W_p, wph, wpl, E_, HI_);
    tsplit_kernel<<<dim3(E_ / 32, HI_ / 32), dim3(32, 8)>>>(W_o, woh, wol, HI_, E_);

    // ---- tensor-core linears (HMMA bf16x3) ----
    hmma_gemm<<<dim3(HI_ / 128, (S_ * B_) / 128), 256, GM_SMEM>>>(
        xhi + (size_t)P_ * B_ * E_, xlo + (size_t)P_ * B_ * E_,
        wqh, wql, nullptr, pq, S_ * B_, HI_, E_);
    hmma_gemm<<<dim3(2 * HI_ / 128, (J_ * B_) / 128), 256, GM_SMEM>>>(
        xhi, xlo, wkh, wkl, nullptr, pkv, J_ * B_, 2 * HI_, E_);
    hmma_gemm<<<dim3(HI_ / 128, J_ / 128), 256, GM_SMEM>>>(
        pehi, pelo, wph, wpl, nullptr, pp, J_, HI_, E_);

    // ---- attention ----
    scores_kernel<<<dim3(J_ / 64, S_ / 64, B_ * H_), 256, SC_SMEM_BYTES>>>(u, v);
    softmax_kernel<<<dim3(S_, B_ * H_), 256>>>();
    awv_kernel<<<dim3(S_ / 128, B_ * H_), 256>>>();

    // ---- output projection + residual ----
    split_kernel<<<4096, 256>>>(pawv, ahi, alo, S_ * B_ * HI_);
    hmma_gemm<<<dim3(E_ / 128, (S_ * B_) / 128), 256, GM_SMEM>>>(
        ahi, alo, woh, wol, inputMHA, po, S_ * B_, E_, HI_);

    // ---- LayerNorm ----
    ln_kernel<<<S_ * B_, 256>>>(gamma, beta, (float*)d_out);
}

// round 10
// speedup vs baseline: 1.2574x; 1.2574x over previous
#include <cuda_runtime.h>
#include <cuda_bf16.h>
#include <cstdint>
#include <cstddef>

#define S_  1024
#define P_  1024
#define J_  2048
#define B_  4
#define E_  1024
#define H_  16
#define I_  64
#define HI_ 1024

// ---------------- fp32 scratch ----------------------------------------------
__device__ float g_q[(size_t)S_ * B_ * HI_];          // (S,B,H*I)
__device__ float g_kv[(size_t)J_ * B_ * 2 * HI_];     // (J,B,2*H*I)  keys | values
__device__ float g_p[(size_t)J_ * HI_];               // (J,H*I)
__device__ float g_sc[(size_t)B_ * H_ * S_ * J_];     // (B*H, S, J) logits
__device__ float g_awv[(size_t)S_ * B_ * HI_];        // (S,B,H*I)
__device__ float g_o[(size_t)S_ * B_ * E_];           // pre-LN output

// ---------------- bf16 scratch ----------------------------------------------
__device__ __nv_bfloat16 g_xhi[(size_t)8192 * 1024];   // [memory ; inputMHA] hi
__device__ __nv_bfloat16 g_pehi[(size_t)2048 * 1024];  // posEmb hi
__device__ __nv_bfloat16 g_ahi[(size_t)4096 * 1024];   // awv hi
__device__ __nv_bfloat16 g_pb[(size_t)B_ * H_ * S_ * J_];  // probs bf16
__device__ __nv_bfloat16 g_vt[(size_t)B_ * H_ * 64 * J_];  // V^T per (b,h): [i][j]
__device__ __nv_bfloat16 g_wqhi[(size_t)1024 * 1024];  // W^T [N,K] hi/lo
__device__ __nv_bfloat16 g_wqlo[(size_t)1024 * 1024];
__device__ __nv_bfloat16 g_wkvhi[(size_t)2048 * 1024];
__device__ __nv_bfloat16 g_wkvlo[(size_t)2048 * 1024];
__device__ __nv_bfloat16 g_wphi[(size_t)1024 * 1024];
__device__ __nv_bfloat16 g_wplo[(size_t)1024 * 1024];
__device__ __nv_bfloat16 g_wohi[(size_t)1024 * 1024];
__device__ __nv_bfloat16 g_wolo[(size_t)1024 * 1024];

// ---------------- small helpers ---------------------------------------------
__device__ __forceinline__ uint32_t smem_u32(const void* p) {
    uint32_t a;
    asm("{ .reg .u64 t; cvta.to.shared.u64 t, %1; cvt.u32.u64 %0, t; }"
        : "=r"(a) : "l"(p));
    return a;
}
__device__ __forceinline__ void cpa16(uint32_t s, const void* g) {
    asm volatile("cp.async.cg.shared.global [%0], [%1], 16;" :: "r"(s), "l"(g));
}
__device__ __forceinline__ void ldm_x4(uint32_t* d, uint32_t addr) {
    asm volatile("ldmatrix.sync.aligned.m8n8.x4.shared.b16 {%0,%1,%2,%3}, [%4];"
                 : "=r"(d[0]), "=r"(d[1]), "=r"(d[2]), "=r"(d[3]) : "r"(addr));
}
__device__ __forceinline__ void ldm_x2(uint32_t* d, uint32_t addr) {
    asm volatile("ldmatrix.sync.aligned.m8n8.x2.shared.b16 {%0,%1}, [%2];"
                 : "=r"(d[0]), "=r"(d[1]) : "r"(addr));
}
__device__ __forceinline__ void mma16816(float* c, const uint32_t* a, const uint32_t* b) {
    asm volatile("mma.sync.aligned.m16n8k16.row.col.f32.bf16.bf16.f32 "
                 "{%0,%1,%2,%3},{%4,%5,%6,%7},{%8,%9},{%0,%1,%2,%3};"
                 : "+f"(c[0]), "+f"(c[1]), "+f"(c[2]), "+f"(c[3])
                 : "r"(a[0]), "r"(a[1]), "r"(a[2]), "r"(a[3]), "r"(b[0]), "r"(b[1]));
}

// ---------------- HMMA bf16x2 GEMM: C = A_hi*(B_hi+B_lo)^T (+res) -----------
// CTA tile 128x128, 8 warps (warp tile 64x32), K-chunk 32, 3-stage cp.async.
// Per stage: A (hi only), Bhi, Blo.
#define ROWB   80            // padded row stride in bytes (32 bf16 + 8 pad)
#define TILEB  (128 * ROWB)  // 10240
#define STG    (3 * TILEB)   // 30720
#define NSTG   3
#define GM_SMEM (NSTG * STG) // 92160 -> 2 CTAs/SM

__device__ __forceinline__ void gload(uint32_t dst, const __nv_bfloat16* src,
                                      int row0, int ld, int k0, int tid) {
#pragma unroll
    for (int it = 0; it < 2; it++) {
        int idx = it * 256 + tid;
        int r = idx >> 2, c = idx & 3;
        cpa16(dst + r * ROWB + c * 16, src + (size_t)(row0 + r) * ld + k0 + c * 8);
    }
}

__global__ __launch_bounds__(256) void hmma_gemm(const __nv_bfloat16* __restrict__ Ahi,
                                                 const __nv_bfloat16* __restrict__ Bhi,
                                                 const __nv_bfloat16* __restrict__ Blo,
                                                 const float* __restrict__ res,
                                                 float* __restrict__ C,
                                                 int M, int N, int K) {
    extern __shared__ char smc[];
    uint32_t sb = smem_u32(smc);
    int tid = threadIdx.x, wid = tid >> 5, lane = tid & 31;
    int wm = wid & 1, wn = wid >> 1;            // warp grid 2 x 4
    int m0 = blockIdx.y * 128, n0 = blockIdx.x * 128;

    float acc[4][4][4];
#pragma unroll
    for (int t = 0; t < 4; t++)
#pragma unroll
        for (int s = 0; s < 4; s++)
#pragma unroll
            for (int r = 0; r < 4; r++) acc[t][s][r] = 0.f;

    const int NC = K / 32;
#pragma unroll
    for (int st = 0; st < 2; st++) {
        uint32_t base = sb + st * STG;
        gload(base,             Ahi, m0, K, st * 32, tid);
        gload(base + TILEB,     Bhi, n0, K, st * 32, tid);
        gload(base + 2 * TILEB, Blo, n0, K, st * 32, tid);
        asm volatile("cp.async.commit_group;" ::: "memory");
    }

    int a_row = (lane & 15), a_hi16 = (lane >> 4) * 16;
    int b_row = (lane & 7), b_hi16 = ((lane >> 3) & 1) * 16;

    for (int c = 0; c < NC; c++) {
        if (c + 2 < NC) {
            uint32_t base = sb + ((c + 2) % NSTG) * STG;
            gload(base,             Ahi, m0, K, (c + 2) * 32, tid);
            gload(base + TILEB,     Bhi, n0, K, (c + 2) * 32, tid);
            gload(base + 2 * TILEB, Blo, n0, K, (c + 2) * 32, tid);
        }
        asm volatile("cp.async.commit_group;" ::: "memory");
        asm volatile("cp.async.wait_group 2;" ::: "memory");
        __syncthreads();

        uint32_t base = sb + (c % NSTG) * STG;
        uint32_t aH = base, bH = base + TILEB, bL = base + 2 * TILEB;
#pragma unroll
        for (int kk = 0; kk < 2; kk++) {
            uint32_t ah[4][4], bh[4][2], bl[4][2];
#pragma unroll
            for (int t = 0; t < 4; t++) {
                uint32_t off = (uint32_t)((wm * 64 + t * 16 + a_row) * ROWB + kk * 32 + a_hi16);
                ldm_x4(ah[t], aH + off);
            }
#pragma unroll
            for (int s = 0; s < 4; s++) {
                uint32_t off = (uint32_t)((wn * 32 + s * 8 + b_row) * ROWB + kk * 32 + b_hi16);
                ldm_x2(bh[s], bH + off);
                ldm_x2(bl[s], bL + off);
            }
#pragma unroll
            for (int t = 0; t < 4; t++)
#pragma unroll
                for (int s = 0; s < 4; s++)
                    mma16816(acc[t][s], ah[t], bh[s]);
#pragma unroll
            for (int t = 0; t < 4; t++)
#pragma unroll
                for (int s = 0; s < 4; s++)
                    mma16816(acc[t][s], ah[t], bl[s]);
        }
        __syncthreads();
    }

#pragma unroll
    for (int t = 0; t < 4; t++) {
        int mg = m0 + wm * 64 + t * 16 + (lane >> 2);
#pragma unroll
        for (int s = 0; s < 4; s++) {
            int ng = n0 + wn * 32 + s * 8 + (lane & 3) * 2;
            float2 v0 = make_float2(acc[t][s][0], acc[t][s][1]);
            float2 v1 = make_float2(acc[t][s][2], acc[t][s][3]);
            if (res) {
                float2 r0 = *(const float2*)&res[(size_t)mg * N + ng];
                float2 r1 = *(const float2*)&res[(size_t)(mg + 8) * N + ng];
                v0.x += r0.x; v0.y += r0.y; v1.x += r1.x; v1.y += r1.y;
            }
            *(float2*)&C[(size_t)mg * N + ng] = v0;
            *(float2*)&C[(size_t)(mg + 8) * N + ng] = v1;
        }
    }
}

// ---------------- awv = probs(bf16) @ V(bf16), HMMA x1 ----------------------
// Per (b,h): C[128 s x 64 i], K-loop over j (skip all-zero tail).
#define AV_ATILE (128 * ROWB)          // 10240
#define AV_BTILE (64 * ROWB)           // 5120
#define AV_STG   (AV_ATILE + AV_BTILE) // 15360
#define AV_SMEM  (3 * AV_STG)          // 46080

__global__ __launch_bounds__(256) void awv_hmma() {
    extern __shared__ char smc[];
    uint32_t sb = smem_u32(smc);
    int tid = threadIdx.x, wid = tid >> 5, lane = tid & 31;
    int wm = wid & 3, wn = wid >> 2;    // warp grid 4(m) x 2(n), warp tile 32x32
    int bh = blockIdx.y;
    int b = bh >> 4, h = bh & 15;
    int s0 = blockIdx.x * 128;
    const __nv_bfloat16* A = g_pb + ((size_t)bh * S_ + s0) * J_;
    const __nv_bfloat16* Bv = g_vt + (size_t)bh * 64 * J_;
    const int NC = (P_ + s0 + 128) / 32;

    float acc[2][4][4];
#pragma unroll
    for (int t = 0; t < 2; t++)
#pragma unroll
        for (int s = 0; s < 4; s++)
#pragma unroll
            for (int r = 0; r < 4; r++) acc[t][s][r] = 0.f;

#pragma unroll
    for (int st = 0; st < 2; st++) {
        uint32_t base = sb + st * AV_STG;
        int k0 = st * 32;
#pragma unroll
        for (int it = 0; it < 2; it++) {
            int idx = it * 256 + tid;
            int r = idx >> 2, c = idx & 3;
            cpa16(base + r * ROWB + c * 16, A + (size_t)r * J_ + k0 + c * 8);
        }
        {
            int r = tid >> 2, c = tid & 3;
            cpa16(base + AV_ATILE + r * ROWB + c * 16, Bv + (size_t)r * J_ + k0 + c * 8);
        }
        asm volatile("cp.async.commit_group;" ::: "memory");
    }

    int a_row = (lane & 15), a_hi16 = (lane >> 4) * 16;
    int b_row = (lane & 7), b_hi16 = ((lane >> 3) & 1) * 16;

    for (int c = 0; c < NC; c++) {
        if (c + 2 < NC) {
            uint32_t base = sb + ((c + 2) % 3) * AV_STG;
            int k0 = (c + 2) * 32;
#pragma unroll
            for (int it = 0; it < 2; it++) {
                int idx = it * 256 + tid;
                int r = idx >> 2, cc = idx & 3;
                cpa16(base + r * ROWB + cc * 16, A + (size_t)r * J_ + k0 + cc * 8);
            }
            {
                int r = tid >> 2, cc = tid & 3;
                cpa16(base + AV_ATILE + r * ROWB + cc * 16, Bv + (size_t)r * J_ + k0 + cc * 8);
            }
        }
        asm volatile("cp.async.commit_group;" ::: "memory");
        asm volatile("cp.async.wait_group 2;" ::: "memory");
        __syncthreads();

        uint32_t base = sb + (c % 3) * AV_STG;
        uint32_t aP = base, bV = base + AV_ATILE;
#pragma unroll
        for (int kk = 0; kk < 2; kk++) {
            uint32_t ap[2][4], bv[4][2];
#pragma unroll
            for (int t = 0; t < 2; t++) {
                uint32_t off = (uint32_t)((wm * 32 + t * 16 + a_row) * ROWB + kk * 32 + a_hi16);
                ldm_x4(ap[t], aP + off);
            }
#pragma unroll
            for (int s = 0; s < 4; s++) {
                uint32_t off = (uint32_t)((wn * 32 + s * 8 + b_row) * ROWB + kk * 32 + b_hi16);
                ldm_x2(bv[s], bV + off);
            }
#pragma unroll
            for (int t = 0; t < 2; t++)
#pragma unroll
                for (int s = 0; s < 4; s++)
                    mma16816(acc[t][s], ap[t], bv[s]);
        }
        __syncthreads();
    }

#pragma unroll
    for (int t = 0; t < 2; t++) {
        int sg = s0 + wm * 32 + t * 16 + (lane >> 2);
#pragma unroll
        for (int s = 0; s < 4; s++) {
            int ig = wn * 32 + s * 8 + (lane & 3) * 2;
            *(float2*)&g_awv[((size_t)sg * B_ + b) * HI_ + h * 64 + ig] =
                make_float2(acc[t][s][0], acc[t][s][1]);
            *(float2*)&g_awv[((size_t)(sg + 8) * B_ + b) * HI_ + h * 64 + ig] =
                make_float2(acc[t][s][2], acc[t][s][3]);
        }
    }
}

// ---------------- fp32 -> bf16 (hi only) ------------------------------------
__global__ __launch_bounds__(256) void cvt_kernel(const float* __restrict__ x,
                                                  __nv_bfloat16* __restrict__ hi,
                                                  int n) {
    int i = (blockIdx.x * 256 + threadIdx.x) * 4;
    if (i >= n) return;
    float4 v = *(const float4*)&x[i];
    __nv_bfloat162 h0, h1;
    h0.x = __float2bfloat16(v.x); h0.y = __float2bfloat16(v.y);
    h1.x = __float2bfloat16(v.z); h1.y = __float2bfloat16(v.w);
    *(__nv_bfloat162*)&hi[i] = h0;
    *(__nv_bfloat162*)&hi[i + 2] = h1;
}

// ---------------- W[K,N] -> T[N,K] transpose + hi/lo split ------------------
__global__ void tsplit_kernel(const float* __restrict__ W,
                              __nv_bfloat16* __restrict__ Thi,
                              __nv_bfloat16* __restrict__ Tlo,
                              int Kd, int Nd) {
    __shared__ float t[32][33];
    int n0 = blockIdx.x * 32, k0 = blockIdx.y * 32;
    int tx = threadIdx.x, ty = threadIdx.y;
#pragma unroll
    for (int r = 0; r < 32; r += 8)
        t[ty + r][tx] = W[(size_t)(k0 + ty + r) * Nd + n0 + tx];
    __syncthreads();
#pragma unroll
    for (int r = 0; r < 32; r += 8) {
        float v = t[tx][ty + r];
        __nv_bfloat16 h = __float2bfloat16(v);
        Thi[(size_t)(n0 + ty + r) * Kd + k0 + tx] = h;
        Tlo[(size_t)(n0 + ty + r) * Kd + k0 + tx] =
            __float2bfloat16(v - __bfloat162float(h));
    }
}

// ---------------- values -> V^T bf16 per (b,h): [i][j] ----------------------
__global__ void vt_kernel() {
    __shared__ float t[32][33];
    int j0 = blockIdx.x * 32, i0 = blockIdx.y * 32;
    int bh = blockIdx.z;
    int b = bh >> 4, h = bh & 15;
    int tx = threadIdx.x, ty = threadIdx.y;
#pragma unroll
    for (int r = 0; r < 32; r += 8)
        t[ty + r][tx] = g_kv[((size_t)(j0 + ty + r) * B_ + b) * (2 * HI_) + HI_ + h * 64 + i0 + tx];
    __syncthreads();
#pragma unroll
    for (int r = 0; r < 32; r += 8)
        g_vt[((size_t)bh * 64 + i0 + ty + r) * J_ + j0 + tx] =
            __float2bfloat16(t[tx][ty + r]);
}

// ---------------- scores: content + rel-shifted position, mask, scale ------
#define SC_SMEM_FLOATS (2 * 64 * 65 + 128 * 65 + 64)
#define SC_SMEM_BYTES  (SC_SMEM_FLOATS * 4)

__global__ __launch_bounds__(256) void scores_kernel(const float* __restrict__ u,
                                                     const float* __restrict__ vvec) {
    int bh = blockIdx.z;
    int b = bh >> 4, h = bh & 15;
    int s0 = blockIdx.y << 6, j0 = blockIdx.x << 6;
    int tid = threadIdx.x;
    float* out = g_sc + ((size_t)bh * S_ + s0) * J_ + j0;

    if (j0 > P_ + s0 + 63) {
        float4 m4 = make_float4(-1e30f, -1e30f, -1e30f, -1e30f);
#pragma unroll
        for (int it = 0; it < 4; it++) {
            int idx = it * 256 + tid;
            int r = idx >> 4, c = (idx & 15) << 2;
            *(float4*)&out[(size_t)r * J_ + c] = m4;
        }
        return;
    }

    extern __shared__ float smf[];
    float* qu_s = smf;
    float* K_s  = smf + 64 * 65;
    float* p_s  = smf + 2 * 64 * 65;
    float* w_s  = smf + 2 * 64 * 65 + 128 * 65;

    if (tid < 64) w_s[tid] = vvec[h * 64 + tid] - u[h * 64 + tid];

#pragma unroll
    for (int it = 0; it < 4; it++) {
        int idx = it * 256 + tid;
        int r = idx >> 4, i4 = (idx & 15) << 2;
        float4 q4 = *(const float4*)&g_q[((size_t)(s0 + r) * B_ + b) * HI_ + h * 64 + i4];
        float4 u4 = *(const float4*)&u[h * 64 + i4];
        qu_s[r * 65 + i4 + 0] = q4.x + u4.x;
        qu_s[r * 65 + i4 + 1] = q4.y + u4.y;
        qu_s[r * 65 + i4 + 2] = q4.z + u4.z;
        qu_s[r * 65 + i4 + 3] = q4.w + u4.w;
        float4 k4 = *(const float4*)&g_kv[((size_t)(j0 + r) * B_ + b) * (2 * HI_) + h * 64 + i4];
        K_s[r * 65 + i4 + 0] = k4.x;
        K_s[r * 65 + i4 + 1] = k4.y;
        K_s[r * 65 + i4 + 2] = k4.z;
        K_s[r * 65 + i4 + 3] = k4.w;
    }
    int d0 = j0 - s0 + 960;
#pragma unroll
    for (int it = 0; it < 8; it++) {
        int idx = it * 256 + tid;
        int r = idx >> 4, i4 = (idx & 15) << 2;
        int d = d0 + r;
        float4 p4 = make_float4(0.f, 0.f, 0.f, 0.f);
        if (d >= 0 && d < J_)
            p4 = *(const float4*)&g_p[(size_t)d * HI_ + h * 64 + i4];
        p_s[r * 65 + i4 + 0] = p4.x;
        p_s[r * 65 + i4 + 1] = p4.y;
        p_s[r * 65 + i4 + 2] = p4.z;
        p_s[r * 65 + i4 + 3] = p4.w;
    }
    __syncthreads();

    int tx = tid & 15, ty = tid >> 4;
    float acc[4][4];
#pragma unroll
    for (int r = 0; r < 4; r++)
#pragma unroll
        for (int c = 0; c < 4; c++) acc[r][c] = 0.f;

    int pb = (tx << 2) - (ty << 2) + 60;

    for (int i = 0; i < 64; i++) {
        float a[4], av[4], k[4], pv[7];
        float w = w_s[i];
#pragma unroll
        for (int r = 0; r < 4; r++) {
            a[r] = qu_s[((ty << 2) + r) * 65 + i];
            av[r] = a[r] + w;
        }
#pragma unroll
        for (int c = 0; c < 4; c++) k[c] = K_s[((tx << 2) + c) * 65 + i];
#pragma unroll
        for (int d = 0; d < 7; d++) pv[d] = p_s[(pb + d) * 65 + i];
#pragma unroll
        for (int r = 0; r < 4; r++)
#pragma unroll
            for (int c = 0; c < 4; c++)
                acc[r][c] = fmaf(a[r], k[c], fmaf(av[r], pv[c - r + 3], acc[r][c]));
    }

#pragma unroll
    for (int r = 0; r < 4; r++) {
        int s = s0 + (ty << 2) + r;
        int jb = j0 + (tx << 2);
        float4 o4;
        float* po = (float*)&o4;
#pragma unroll
        for (int c = 0; c < 4; c++)
            po[c] = (jb + c <= P_ + s) ? acc[r][c] * 0.125f : -1e30f;
        *(float4*)&out[(size_t)((ty << 2) + r) * J_ + (tx << 2)] = o4;
    }
}

// ---------------- row softmax over J=2048 -> bf16 probs ---------------------
__global__ __launch_bounds__(256) void softmax_kernel() {
    const float* row = g_sc + ((size_t)blockIdx.y * S_ + blockIdx.x) * J_;
    __nv_bfloat16* orow = g_pb + ((size_t)blockIdx.y * S_ + blockIdx.x) * J_;
    int tid = threadIdx.x;
    float4 v0 = *(const float4*)&row[tid * 8];
    float4 v1 = *(const float4*)&row[tid * 8 + 4];
    float m = fmaxf(fmaxf(fmaxf(v0.x, v0.y), fmaxf(v0.z, v0.w)),
                    fmaxf(fmaxf(v1.x, v1.y), fmaxf(v1.z, v1.w)));
    __shared__ float red[8];
#pragma unroll
    for (int o = 16; o > 0; o >>= 1) m = fmaxf(m, __shfl_xor_sync(0xffffffffu, m, o));
    if ((tid & 31) == 0) red[tid >> 5] = m;
    __syncthreads();
    m = red[0];
#pragma unroll
    for (int i = 1; i < 8; i++) m = fmaxf(m, red[i]);

    v0.x = __expf(v0.x - m); v0.y = __expf(v0.y - m);
    v0.z = __expf(v0.z - m); v0.w = __expf(v0.w - m);
    v1.x = __expf(v1.x - m); v1.y = __expf(v1.y - m);
    v1.z = __expf(v1.z - m); v1.w = __expf(v1.w - m);
    float s = v0.x + v0.y + v0.z + v0.w + v1.x + v1.y + v1.z + v1.w;
    __syncthreads();
#pragma unroll
    for (int o = 16; o > 0; o >>= 1) s += __shfl_xor_sync(0xffffffffu, s, o);
    if ((tid & 31) == 0) red[tid >> 5] = s;
    __syncthreads();
    s = 0.f;
#pragma unroll
    for (int i = 0; i < 8; i++) s += red[i];
    float inv = 1.0f / s;
    __nv_bfloat162 o0, o1, o2, o3;
    o0.x = __float2bfloat16(v0.x * inv); o0.y = __float2bfloat16(v0.y * inv);
    o1.x = __float2bfloat16(v0.z * inv); o1.y = __float2bfloat16(v0.w * inv);
    o2.x = __float2bfloat16(v1.x * inv); o2.y = __float2bfloat16(v1.y * inv);
    o3.x = __float2bfloat16(v1.z * inv); o3.y = __float2bfloat16(v1.w * inv);
    *(__nv_bfloat162*)&orow[tid * 8]     = o0;
    *(__nv_bfloat162*)&orow[tid * 8 + 2] = o1;
    *(__nv_bfloat162*)&orow[tid * 8 + 4] = o2;
    *(__nv_bfloat162*)&orow[tid * 8 + 6] = o3;
}

// ---------------- LayerNorm over E=1024 ------------------------------------
__global__ __launch_bounds__(256) void ln_kernel(const float* __restrict__ gamma,
                                                 const float* __restrict__ beta,
                                                 float* __restrict__ out) {
    int row = blockIdx.x;
    const float* x = g_o + (size_t)row * E_;
    int tid = threadIdx.x;
    float4 v = *(const float4*)&x[tid << 2];
    float s1 = v.x + v.y + v.z + v.w;
    float s2 = v.x * v.x + v.y * v.y + v.z * v.z + v.w * v.w;
    __shared__ float r1[8], r2[8];
#pragma unroll
    for (int o = 16; o > 0; o >>= 1) {
        s1 += __shfl_xor_sync(0xffffffffu, s1, o);
        s2 += __shfl_xor_sync(0xffffffffu, s2, o);
    }
    if ((tid & 31) == 0) { r1[tid >> 5] = s1; r2[tid >> 5] = s2; }
    __syncthreads();
    float S1 = 0.f, S2 = 0.f;
#pragma unroll
    for (int i = 0; i < 8; i++) { S1 += r1[i]; S2 += r2[i]; }
    float mean = S1 * (1.0f / E_);
    float var = S2 * (1.0f / E_) - mean * mean;
    float rstd = rsqrtf(var + 1e-5f);
    float4 g = *(const float4*)&gamma[tid << 2];
    float4 bb = *(const float4*)&beta[tid << 2];
    float4 o;
    o.x = (v.x - mean) * rstd * g.x + bb.x;
    o.y = (v.y - mean) * rstd * g.y + bb.y;
    o.z = (v.z - mean) * rstd * g.z + bb.z;
    o.w = (v.w - mean) * rstd * g.w + bb.w;
    *(float4*)&out[(size_t)row * E_ + (tid << 2)] = o;
}

// ---------------- launch ----------------------------------------------------
extern "C" void kernel_launch(void* const* d_in, const int* in_sizes, int n_in,
                              void* d_out, int out_size) {
    (void)in_sizes; (void)n_in; (void)out_size;
    const float* inputMHA = (const float*)d_in[0];
    const float* posEmb   = (const float*)d_in[1];
    const float* memory   = (const float*)d_in[2];
    const float* u        = (const float*)d_in[3];
    const float* v        = (const float*)d_in[4];
    const float* W_kv     = (const float*)d_in[6];
    const float* W_q      = (const float*)d_in[7];
    const float* W_p      = (const float*)d_in[8];
    const float* W_o      = (const float*)d_in[9];
    const float* gamma    = (const float*)d_in[10];
    const float* beta     = (const float*)d_in[11];

    float *pq, *pkv, *pp, *pawv, *po;
    cudaGetSymbolAddress((void**)&pq, g_q);
    cudaGetSymbolAddress((void**)&pkv, g_kv);
    cudaGetSymbolAddress((void**)&pp, g_p);
    cudaGetSymbolAddress((void**)&pawv, g_awv);
    cudaGetSymbolAddress((void**)&po, g_o);

    __nv_bfloat16 *xhi, *pehi, *ahi;
    __nv_bfloat16 *wqh, *wql, *wkh, *wkl, *wph, *wpl, *woh, *wol;
    cudaGetSymbolAddress((void**)&xhi, g_xhi);
    cudaGetSymbolAddress((void**)&pehi, g_pehi);
    cudaGetSymbolAddress((void**)&ahi, g_ahi);
    cudaGetSymbolAddress((void**)&wqh, g_wqhi);
    cudaGetSymbolAddress((void**)&wql, g_wqlo);
    cudaGetSymbolAddress((void**)&wkh, g_wkvhi);
    cudaGetSymbolAddress((void**)&wkl, g_wkvlo);
    cudaGetSymbolAddress((void**)&wph, g_wphi);
    cudaGetSymbolAddress((void**)&wpl, g_wplo);
    cudaGetSymbolAddress((void**)&woh, g_wohi);
    cudaGetSymbolAddress((void**)&wol, g_wolo);

    cudaFuncSetAttribute(scores_kernel, cudaFuncAttributeMaxDynamicSharedMemorySize,
                         SC_SMEM_BYTES);
    cudaFuncSetAttribute(hmma_gemm, cudaFuncAttributeMaxDynamicSharedMemorySize, GM_SMEM);
    cudaFuncSetAttribute(awv_hmma, cudaFuncAttributeMaxDynamicSharedMemorySize, AV_SMEM);

    // ---- convert inputs to bf16 (activations hi-only; weights hi+lo T) ----
    cvt_kernel<<<4096, 256>>>(memory, xhi, P_ * B_ * E_);
    cvt_kernel<<<4096, 256>>>(inputMHA, xhi + (size_t)P_ * B_ * E_, S_ * B_ * E_);
    cvt_kernel<<<2048, 256>>>(posEmb, pehi, J_ * E_);
    tsplit_kernel<<<dim3(HI_ / 32, E_ / 32), dim3(32, 8)>>>(W_q, wqh, wql, E_, HI_);
    tsplit_kernel<<<dim3(2 * HI_ / 32, E_ / 32), dim3(32, 8)>>>(W_kv, wkh, wkl, E_, 2 * HI_);
    tsplit_kernel<<<dim3(HI_ / 32, E_ / 32), dim3(32, 8)>>>(W_p, wph, wpl, E_, HI_);
    tsplit_kernel<<<dim3(E_ / 32, HI_ / 32), dim3(32, 8)>>>(W_o, woh, wol, HI_, E_);

    // ---- linears (HMMA bf16x2) ----
    hmma_gemm<<<dim3(HI_ / 128, (S_ * B_) / 128), 256, GM_SMEM>>>(
        xhi + (size_t)P_ * B_ * E_, wqh, wql, nullptr, pq, S_ * B_, HI_, E_);
    hmma_gemm<<<dim3(2 * HI_ / 128, (J_ * B_) / 128), 256, GM_SMEM>>>(
        xhi, wkh, wkl, nullptr, pkv, J_ * B_, 2 * HI_, E_);
    hmma_gemm<<<dim3(HI_ / 128, J_ / 128), 256, GM_SMEM>>>(
        pehi, wph, wpl, nullptr, pp, J_, HI_, E_);

    // ---- V^T bf16 for awv ----
    vt_kernel<<<dim3(J_ / 32, 2, B_ * H_), dim3(32, 8)>>>();

    // ---- attention ----
    scores_kernel<<<dim3(J_ / 64, S_ / 64, B_ * H_), 256, SC_SMEM_BYTES>>>(u, v);
    softmax_kernel<<<dim3(S_, B_ * H_), 256>>>();
    awv_hmma<<<dim3(S_ / 128, B_ * H_), 256, AV_SMEM>>>();

    // ---- output projection + residual ----
    cvt_kernel<<<4096, 256>>>(pawv, ahi, S_ * B_ * HI_);
    hmma_gemm<<<dim3(E_ / 128, (S_ * B_) / 128), 256, GM_SMEM>>>(
        ahi, woh, wol, inputMHA, po, S_ * B_, E_, HI_);

    // ---- LayerNorm ----
    ln_kernel<<<S_ * B_, 256>>>(gamma, beta, (float*)d_out);
}

// round 12
// speedup vs baseline: 2.8877x; 2.2966x over previous
#include <cuda_runtime.h>
#include <cuda_bf16.h>
#include <cstdint>
#include <cstddef>

#define S_  1024
#define P_  1024
#define J_  2048
#define B_  4
#define E_  1024
#define H_  16
#define I_  64
#define HI_ 1024

// ---------------- fp32 scratch ----------------------------------------------
__device__ float g_q[(size_t)S_ * B_ * HI_];          // (S,B,H*I)
__device__ float g_kv[(size_t)J_ * B_ * 2 * HI_];     // (J,B,2*H*I)  keys | values
__device__ float g_p[(size_t)J_ * HI_];               // (J,H*I)
__device__ float g_sc[(size_t)B_ * H_ * S_ * J_];     // (B*H, S, J) logits
__device__ float g_awv[(size_t)S_ * B_ * HI_];        // (S,B,H*I)
__device__ float g_o[(size_t)S_ * B_ * E_];           // pre-LN output

// ---------------- bf16 scratch ----------------------------------------------
__device__ __nv_bfloat16 g_xhi[(size_t)8192 * 1024];   // [memory ; inputMHA] hi
__device__ __nv_bfloat16 g_pehi[(size_t)2048 * 1024];  // posEmb hi
__device__ __nv_bfloat16 g_ahi[(size_t)4096 * 1024];   // awv hi
__device__ __nv_bfloat16 g_pb[(size_t)B_ * H_ * S_ * J_];  // probs bf16
__device__ __nv_bfloat16 g_vt[(size_t)B_ * H_ * 64 * J_];  // V^T per (b,h): [i][j]
__device__ __nv_bfloat16 g_qub[(size_t)S_ * B_ * HI_];  // bf16(q+u)
__device__ __nv_bfloat16 g_qvb[(size_t)S_ * B_ * HI_];  // bf16(q+v)
__device__ __nv_bfloat16 g_kb[(size_t)J_ * B_ * HI_];   // keys bf16
__device__ __nv_bfloat16 g_ppb[(size_t)J_ * HI_];       // p bf16
__device__ __nv_bfloat16 g_wqhi[(size_t)1024 * 1024];  // W^T [N,K] hi/lo
__device__ __nv_bfloat16 g_wqlo[(size_t)1024 * 1024];
__device__ __nv_bfloat16 g_wkvhi[(size_t)2048 * 1024];
__device__ __nv_bfloat16 g_wkvlo[(size_t)2048 * 1024];
__device__ __nv_bfloat16 g_wphi[(size_t)1024 * 1024];
__device__ __nv_bfloat16 g_wplo[(size_t)1024 * 1024];
__device__ __nv_bfloat16 g_wohi[(size_t)1024 * 1024];
__device__ __nv_bfloat16 g_wolo[(size_t)1024 * 1024];

// ---------------- small helpers ---------------------------------------------
__device__ __forceinline__ uint32_t smem_u32(const void* p) {
    uint32_t a;
    asm("{ .reg .u64 t; cvta.to.shared.u64 t, %1; cvt.u32.u64 %0, t; }"
        : "=r"(a) : "l"(p));
    return a;
}
__device__ __forceinline__ void cpa16(uint32_t s, const void* g) {
    asm volatile("cp.async.cg.shared.global [%0], [%1], 16;" :: "r"(s), "l"(g));
}
__device__ __forceinline__ void ldm_x4(uint32_t* d, uint32_t addr) {
    asm volatile("ldmatrix.sync.aligned.m8n8.x4.shared.b16 {%0,%1,%2,%3}, [%4];"
                 : "=r"(d[0]), "=r"(d[1]), "=r"(d[2]), "=r"(d[3]) : "r"(addr));
}
__device__ __forceinline__ void ldm_x2(uint32_t* d, uint32_t addr) {
    asm volatile("ldmatrix.sync.aligned.m8n8.x2.shared.b16 {%0,%1}, [%2];"
                 : "=r"(d[0]), "=r"(d[1]) : "r"(addr));
}
__device__ __forceinline__ void mma16816(float* c, const uint32_t* a, const uint32_t* b) {
    asm volatile("mma.sync.aligned.m16n8k16.row.col.f32.bf16.bf16.f32 "
                 "{%0,%1,%2,%3},{%4,%5,%6,%7},{%8,%9},{%0,%1,%2,%3};"
                 : "+f"(c[0]), "+f"(c[1]), "+f"(c[2]), "+f"(c[3])
                 : "r"(a[0]), "r"(a[1]), "r"(a[2]), "r"(a[3]), "r"(b[0]), "r"(b[1]));
}

// ---------------- HMMA bf16x2 GEMM: C = A_hi*(B_hi+B_lo)^T (+res) -----------
#define ROWB   80            // padded row stride in bytes (32 bf16 + 8 pad)
#define TILEB  (128 * ROWB)  // 10240
#define STG    (3 * TILEB)   // 30720
#define NSTG   3
#define GM_SMEM (NSTG * STG) // 92160 -> 2 CTAs/SM

__device__ __forceinline__ void gload(uint32_t dst, const __nv_bfloat16* src,
                                      int row0, int ld, int k0, int tid) {
#pragma unroll
    for (int it = 0; it < 2; it++) {
        int idx = it * 256 + tid;
        int r = idx >> 2, c = idx & 3;
        cpa16(dst + r * ROWB + c * 16, src + (size_t)(row0 + r) * ld + k0 + c * 8);
    }
}

__global__ __launch_bounds__(256) void hmma_gemm(const __nv_bfloat16* __restrict__ Ahi,
                                                 const __nv_bfloat16* __restrict__ Bhi,
                                                 const __nv_bfloat16* __restrict__ Blo,
                                                 const float* __restrict__ res,
                                                 float* __restrict__ C,
                                                 int M, int N, int K) {
    extern __shared__ char smc[];
    uint32_t sb = smem_u32(smc);
    int tid = threadIdx.x, wid = tid >> 5, lane = tid & 31;
    int wm = wid & 1, wn = wid >> 1;
    int m0 = blockIdx.y * 128, n0 = blockIdx.x * 128;

    float acc[4][4][4];
#pragma unroll
    for (int t = 0; t < 4; t++)
#pragma unroll
        for (int s = 0; s < 4; s++)
#pragma unroll
            for (int r = 0; r < 4; r++) acc[t][s][r] = 0.f;

    const int NC = K / 32;
#pragma unroll
    for (int st = 0; st < 2; st++) {
        uint32_t base = sb + st * STG;
        gload(base,             Ahi, m0, K, st * 32, tid);
        gload(base + TILEB,     Bhi, n0, K, st * 32, tid);
        gload(base + 2 * TILEB, Blo, n0, K, st * 32, tid);
        asm volatile("cp.async.commit_group;" ::: "memory");
    }

    int a_row = (lane & 15), a_hi16 = (lane >> 4) * 16;
    int b_row = (lane & 7), b_hi16 = ((lane >> 3) & 1) * 16;

    for (int c = 0; c < NC; c++) {
        if (c + 2 < NC) {
            uint32_t base = sb + ((c + 2) % NSTG) * STG;
            gload(base,             Ahi, m0, K, (c + 2) * 32, tid);
            gload(base + TILEB,     Bhi, n0, K, (c + 2) * 32, tid);
            gload(base + 2 * TILEB, Blo, n0, K, (c + 2) * 32, tid);
        }
        asm volatile("cp.async.commit_group;" ::: "memory");
        asm volatile("cp.async.wait_group 2;" ::: "memory");
        __syncthreads();

        uint32_t base = sb + (c % NSTG) * STG;
        uint32_t aH = base, bH = base + TILEB, bL = base + 2 * TILEB;
#pragma unroll
        for (int kk = 0; kk < 2; kk++) {
            uint32_t ah[4][4], bh[4][2], bl[4][2];
#pragma unroll
            for (int t = 0; t < 4; t++) {
                uint32_t off = (uint32_t)((wm * 64 + t * 16 + a_row) * ROWB + kk * 32 + a_hi16);
                ldm_x4(ah[t], aH + off);
            }
#pragma unroll
            for (int s = 0; s < 4; s++) {
                uint32_t off = (uint32_t)((wn * 32 + s * 8 + b_row) * ROWB + kk * 32 + b_hi16);
                ldm_x2(bh[s], bH + off);
                ldm_x2(bl[s], bL + off);
            }
#pragma unroll
            for (int t = 0; t < 4; t++)
#pragma unroll
                for (int s = 0; s < 4; s++)
                    mma16816(acc[t][s], ah[t], bh[s]);
#pragma unroll
            for (int t = 0; t < 4; t++)
#pragma unroll
                for (int s = 0; s < 4; s++)
                    mma16816(acc[t][s], ah[t], bl[s]);
        }
        __syncthreads();
    }

#pragma unroll
    for (int t = 0; t < 4; t++) {
        int mg = m0 + wm * 64 + t * 16 + (lane >> 2);
#pragma unroll
        for (int s = 0; s < 4; s++) {
            int ng = n0 + wn * 32 + s * 8 + (lane & 3) * 2;
            float2 v0 = make_float2(acc[t][s][0], acc[t][s][1]);
            float2 v1 = make_float2(acc[t][s][2], acc[t][s][3]);
            if (res) {
                float2 r0 = *(const float2*)&res[(size_t)mg * N + ng];
                float2 r1 = *(const float2*)&res[(size_t)(mg + 8) * N + ng];
                v0.x += r0.x; v0.y += r0.y; v1.x += r1.x; v1.y += r1.y;
            }
            *(float2*)&C[(size_t)mg * N + ng] = v0;
            *(float2*)&C[(size_t)(mg + 8) * N + ng] = v1;
        }
    }
}

// ---------------- awv = probs(bf16) @ V(bf16), HMMA x1 ----------------------
#define AV_ATILE (128 * ROWB)
#define AV_BTILE (64 * ROWB)
#define AV_STG   (AV_ATILE + AV_BTILE)
#define AV_SMEM  (3 * AV_STG)

__global__ __launch_bounds__(256) void awv_hmma() {
    extern __shared__ char smc[];
    uint32_t sb = smem_u32(smc);
    int tid = threadIdx.x, wid = tid >> 5, lane = tid & 31;
    int wm = wid & 3, wn = wid >> 2;
    int bh = blockIdx.y;
    int b = bh >> 4, h = bh & 15;
    int s0 = blockIdx.x * 128;
    const __nv_bfloat16* A = g_pb + ((size_t)bh * S_ + s0) * J_;
    const __nv_bfloat16* Bv = g_vt + (size_t)bh * 64 * J_;
    const int NC = (P_ + s0 + 128) / 32;

    float acc[2][4][4];
#pragma unroll
    for (int t = 0; t < 2; t++)
#pragma unroll
        for (int s = 0; s < 4; s++)
#pragma unroll
            for (int r = 0; r < 4; r++) acc[t][s][r] = 0.f;

#pragma unroll
    for (int st = 0; st < 2; st++) {
        uint32_t base = sb + st * AV_STG;
        int k0 = st * 32;
#pragma unroll
        for (int it = 0; it < 2; it++) {
            int idx = it * 256 + tid;
            int r = idx >> 2, c = idx & 3;
            cpa16(base + r * ROWB + c * 16, A + (size_t)r * J_ + k0 + c * 8);
        }
        {
            int r = tid >> 2, c = tid & 3;
            cpa16(base + AV_ATILE + r * ROWB + c * 16, Bv + (size_t)r * J_ + k0 + c * 8);
        }
        asm volatile("cp.async.commit_group;" ::: "memory");
    }

    int a_row = (lane & 15), a_hi16 = (lane >> 4) * 16;
    int b_row = (lane & 7), b_hi16 = ((lane >> 3) & 1) * 16;

    for (int c = 0; c < NC; c++) {
        if (c + 2 < NC) {
            uint32_t base = sb + ((c + 2) % 3) * AV_STG;
            int k0 = (c + 2) * 32;
#pragma unroll
            for (int it = 0; it < 2; it++) {
                int idx = it * 256 + tid;
                int r = idx >> 2, cc = idx & 3;
                cpa16(base + r * ROWB + cc * 16, A + (size_t)r * J_ + k0 + cc * 8);
            }
            {
                int r = tid >> 2, cc = tid & 3;
                cpa16(base + AV_ATILE + r * ROWB + cc * 16, Bv + (size_t)r * J_ + k0 + cc * 8);
            }
        }
        asm volatile("cp.async.commit_group;" ::: "memory");
        asm volatile("cp.async.wait_group 2;" ::: "memory");
        __syncthreads();

        uint32_t base = sb + (c % 3) * AV_STG;
        uint32_t aP = base, bV = base + AV_ATILE;
#pragma unroll
        for (int kk = 0; kk < 2; kk++) {
            uint32_t ap[2][4], bv[4][2];
#pragma unroll
            for (int t = 0; t < 2; t++) {
                uint32_t off = (uint32_t)((wm * 32 + t * 16 + a_row) * ROWB + kk * 32 + a_hi16);
                ldm_x4(ap[t], aP + off);
            }
#pragma unroll
            for (int s = 0; s < 4; s++) {
                uint32_t off = (uint32_t)((wn * 32 + s * 8 + b_row) * ROWB + kk * 32 + b_hi16);
                ldm_x2(bv[s], bV + off);
            }
#pragma unroll
            for (int t = 0; t < 2; t++)
#pragma unroll
                for (int s = 0; s < 4; s++)
                    mma16816(acc[t][s], ap[t], bv[s]);
        }
        __syncthreads();
    }

#pragma unroll
    for (int t = 0; t < 2; t++) {
        int sg = s0 + wm * 32 + t * 16 + (lane >> 2);
#pragma unroll
        for (int s = 0; s < 4; s++) {
            int ig = wn * 32 + s * 8 + (lane & 3) * 2;
            *(float2*)&g_awv[((size_t)sg * B_ + b) * HI_ + h * 64 + ig] =
                make_float2(acc[t][s][0], acc[t][s][1]);
            *(float2*)&g_awv[((size_t)(sg + 8) * B_ + b) * HI_ + h * 64 + ig] =
                make_float2(acc[t][s][2], acc[t][s][3]);
        }
    }
}

// ---------------- fp32 -> bf16 (hi only) ------------------------------------
__global__ __launch_bounds__(256) void cvt_kernel(const float* __restrict__ x,
                                                  __nv_bfloat16* __restrict__ hi,
                                                  int n) {
    int i = (blockIdx.x * 256 + threadIdx.x) * 4;
    if (i >= n) return;
    float4 v = *(const float4*)&x[i];
    __nv_bfloat162 h0, h1;
    h0.x = __float2bfloat16(v.x); h0.y = __float2bfloat16(v.y);
    h1.x = __float2bfloat16(v.z); h1.y = __float2bfloat16(v.w);
    *(__nv_bfloat162*)&hi[i] = h0;
    *(__nv_bfloat162*)&hi[i + 2] = h1;
}

// ---------------- qu/qv bf16: bf16(q + u), bf16(q + v) ----------------------
__global__ __launch_bounds__(256) void quv_kernel(const float* __restrict__ u,
                                                  const float* __restrict__ v) {
    int i = (blockIdx.x * 256 + threadIdx.x) * 4;   // over S*B*HI
    float4 q = *(const float4*)&g_q[i];
    int x = i & (HI_ - 1);
    float4 u4 = *(const float4*)&u[x];
    float4 v4 = *(const float4*)&v[x];
    __nv_bfloat162 a0, a1, b0, b1;
    a0.x = __float2bfloat16(q.x + u4.x); a0.y = __float2bfloat16(q.y + u4.y);
    a1.x = __float2bfloat16(q.z + u4.z); a1.y = __float2bfloat16(q.w + u4.w);
    b0.x = __float2bfloat16(q.x + v4.x); b0.y = __float2bfloat16(q.y + v4.y);
    b1.x = __float2bfloat16(q.z + v4.z); b1.y = __float2bfloat16(q.w + v4.w);
    *(__nv_bfloat162*)&g_qub[i] = a0; *(__nv_bfloat162*)&g_qub[i + 2] = a1;
    *(__nv_bfloat162*)&g_qvb[i] = b0; *(__nv_bfloat162*)&g_qvb[i + 2] = b1;
}

// ---------------- keys -> bf16 [J,B,HI] -------------------------------------
__global__ __launch_bounds__(256) void kb_kernel() {
    int i = (blockIdx.x * 256 + threadIdx.x) * 4;   // over J*B*HI
    int row = i >> 10, x = i & (HI_ - 1);
    float4 k = *(const float4*)&g_kv[((size_t)row << 11) + x];
    __nv_bfloat162 h0, h1;
    h0.x = __float2bfloat16(k.x); h0.y = __float2bfloat16(k.y);
    h1.x = __float2bfloat16(k.z); h1.y = __float2bfloat16(k.w);
    *(__nv_bfloat162*)&g_kb[i] = h0;
    *(__nv_bfloat162*)&g_kb[i + 2] = h1;
}

// ---------------- W[K,N] -> T[N,K] transpose + hi/lo split ------------------
__global__ void tsplit_kernel(const float* __restrict__ W,
                              __nv_bfloat16* __restrict__ Thi,
                              __nv_bfloat16* __restrict__ Tlo,
                              int Kd, int Nd) {
    __shared__ float t[32][33];
    int n0 = blockIdx.x * 32, k0 = blockIdx.y * 32;
    int tx = threadIdx.x, ty = threadIdx.y;
#pragma unroll
    for (int r = 0; r < 32; r += 8)
        t[ty + r][tx] = W[(size_t)(k0 + ty + r) * Nd + n0 + tx];
    __syncthreads();
#pragma unroll
    for (int r = 0; r < 32; r += 8) {
        float v = t[tx][ty + r];
        __nv_bfloat16 h = __float2bfloat16(v);
        Thi[(size_t)(n0 + ty + r) * Kd + k0 + tx] = h;
        Tlo[(size_t)(n0 + ty + r) * Kd + k0 + tx] =
            __float2bfloat16(v - __bfloat162float(h));
    }
}

// ---------------- values -> V^T bf16 per (b,h): [i][j] ----------------------
__global__ void vt_kernel() {
    __shared__ float t[32][33];
    int j0 = blockIdx.x * 32, i0 = blockIdx.y * 32;
    int bh = blockIdx.z;
    int b = bh >> 4, h = bh & 15;
    int tx = threadIdx.x, ty = threadIdx.y;
#pragma unroll
    for (int r = 0; r < 32; r += 8)
        t[ty + r][tx] = g_kv[((size_t)(j0 + ty + r) * B_ + b) * (2 * HI_) + HI_ + h * 64 + i0 + tx];
    __syncthreads();
#pragma unroll
    for (int r = 0; r < 32; r += 8)
        g_vt[((size_t)bh * 64 + i0 + ty + r) * J_ + j0 + tx] =
            __float2bfloat16(t[tx][ty + r]);
}

// ---------------- scores via HMMA: content + rel-shift pos ------------------
// CTA = 64(s) x 64(j) tile for one (b,h); 128 threads (4 warps, 16 s-rows each).
// p window: global p row = j - s + 1023 = (j0-s0+960) + w, w in [0,127].
#define SB_ROW  144                    // 64 bf16 + 8 pad (optimal ldmatrix banks)
#define SC_QU   0
#define SC_QV   (64 * SB_ROW)          // 9216
#define SC_K    (2 * 64 * SB_ROW)      // 18432
#define SC_PW   (3 * 64 * SB_ROW)      // 27648
#define SC_BT   (SC_PW + 128 * SB_ROW) // 46080 (Bt f32 64 x 132)
#define SC_SMEM (SC_BT + 64 * 132 * 4) // 79872

__global__ __launch_bounds__(128) void scores_hmma() {
    int bh = blockIdx.z;
    int b = bh >> 4, h = bh & 15;
    int s0 = blockIdx.y << 6, j0 = blockIdx.x << 6;
    int tid = threadIdx.x;
    float* out = g_sc + ((size_t)bh * S_ + s0) * J_ + j0;

    if (j0 > P_ + s0 + 63) {   // fully masked tile
        float4 m4 = make_float4(-1e30f, -1e30f, -1e30f, -1e30f);
#pragma unroll
        for (int it = 0; it < 8; it++) {
            int idx = it * 128 + tid;
            int r = idx >> 4, c = (idx & 15) << 2;
            *(float4*)&out[(size_t)r * J_ + c] = m4;
        }
        return;
    }

    extern __shared__ char smc[];
    uint32_t sb = smem_u32(smc);
    float* Btf = (float*)(smc + SC_BT);
    int wid = tid >> 5, lane = tid & 31;

    // ---- load Qu, Qv, K tiles (64 rows x 8 16B-chunks each) ----
#pragma unroll
    for (int it = 0; it < 4; it++) {
        int idx = it * 128 + tid;
        int r = idx >> 3, ch = (idx & 7) << 3;   // ch = bf16 col
        *(uint4*)(smc + SC_QU + r * SB_ROW + ch * 2) =
            *(const uint4*)&g_qub[((size_t)(s0 + r) * B_ + b) * HI_ + h * 64 + ch];
        *(uint4*)(smc + SC_QV + r * SB_ROW + ch * 2) =
            *(const uint4*)&g_qvb[((size_t)(s0 + r) * B_ + b) * HI_ + h * 64 + ch];
        *(uint4*)(smc + SC_K + r * SB_ROW + ch * 2) =
            *(const uint4*)&g_kb[((size_t)(j0 + r) * B_ + b) * HI_ + h * 64 + ch];
    }
    // ---- load p window (128 rows, clamp to [0,J)) ----
    int d0 = j0 - s0 + 960;
#pragma unroll
    for (int it = 0; it < 8; it++) {
        int idx = it * 128 + tid;
        int r = idx >> 3, ch = (idx & 7) << 3;
        int d = d0 + r;
        uint4 val = make_uint4(0u, 0u, 0u, 0u);
        if (d >= 0 && d < J_)
            val = *(const uint4*)&g_ppb[(size_t)d * HI_ + h * 64 + ch];
        *(uint4*)(smc + SC_PW + r * SB_ROW + ch * 2) = val;
    }
    __syncthreads();

    int m0w = wid * 16;
    int a_row = lane & 15, a_hi = (lane >> 4) * 16;
    int b_row = lane & 7, b_hi = ((lane >> 3) & 1) * 16;

    // ---- pos: Bt[16 x 128] = Qv_rows @ Pw^T ----
    float accp[16][4];
#pragma unroll
    for (int n = 0; n < 16; n++)
#pragma unroll
        for (int r = 0; r < 4; r++) accp[n][r] = 0.f;
#pragma unroll
    for (int kk = 0; kk < 4; kk++) {
        uint32_t af[4];
        ldm_x4(af, sb + SC_QV + (m0w + a_row) * SB_ROW + kk * 32 + a_hi);
#pragma unroll
        for (int n = 0; n < 16; n++) {
            uint32_t bf[2];
            ldm_x2(bf, sb + SC_PW + (n * 8 + b_row) * SB_ROW + kk * 32 + b_hi);
            mma16816(accp[n], af, bf);
        }
    }
    // write Bt (own rows only -> warp-local)
    {
        int r1 = m0w + (lane >> 2), c0 = (lane & 3) * 2;
#pragma unroll
        for (int n = 0; n < 16; n++) {
            *(float2*)&Btf[r1 * 132 + n * 8 + c0] = make_float2(accp[n][0], accp[n][1]);
            *(float2*)&Btf[(r1 + 8) * 132 + n * 8 + c0] = make_float2(accp[n][2], accp[n][3]);
        }
    }
    __syncwarp();

    // ---- content: C[16 x 64] = Qu_rows @ K^T ----
    float accc[8][4];
#pragma unroll
    for (int n = 0; n < 8; n++)
#pragma unroll
        for (int r = 0; r < 4; r++) accc[n][r] = 0.f;
#pragma unroll
    for (int kk = 0; kk < 4; kk++) {
        uint32_t af[4];
        ldm_x4(af, sb + SC_QU + (m0w + a_row) * SB_ROW + kk * 32 + a_hi);
#pragma unroll
        for (int n = 0; n < 8; n++) {
            uint32_t bf[2];
            ldm_x2(bf, sb + SC_K + (n * 8 + b_row) * SB_ROW + kk * 32 + b_hi);
            mma16816(accc[n], af, bf);
        }
    }

    // ---- combine: logit = (content + Bt[r][c-r+63]) * 0.125, mask ----
    {
        int r1 = m0w + (lane >> 2), c0 = (lane & 3) * 2;
        int r2 = r1 + 8;
#pragma unroll
        for (int n = 0; n < 8; n++) {
            int c = n * 8 + c0;
            float v00 = accc[n][0] + Btf[r1 * 132 + (c - r1 + 63)];
            float v01 = accc[n][1] + Btf[r1 * 132 + (c + 1 - r1 + 63)];
            float v10 = accc[n][2] + Btf[r2 * 132 + (c - r2 + 63)];
            float v11 = accc[n][3] + Btf[r2 * 132 + (c + 1 - r2 + 63)];
            int lim1 = P_ + s0 + r1 - j0;   // keep if c <= lim
            int lim2 = P_ + s0 + r2 - j0;
            float2 o1, o2;
            o1.x = (c     <= lim1) ? v00 * 0.125f : -1e30f;
            o1.y = (c + 1 <= lim1) ? v01 * 0.125f : -1e30f;
            o2.x = (c     <= lim2) ? v10 * 0.125f : -1e30f;
            o2.y = (c + 1 <= lim2) ? v11 * 0.125f : -1e30f;
            *(float2*)&out[(size_t)r1 * J_ + c] = o1;
            *(float2*)&out[(size_t)r2 * J_ + c] = o2;
        }
    }
}

// ---------------- row softmax over J=2048 -> bf16 probs ---------------------
__global__ __launch_bounds__(256) void softmax_kernel() {
    const float* row = g_sc + ((size_t)blockIdx.y * S_ + blockIdx.x) * J_;
    __nv_bfloat16* orow = g_pb + ((size_t)blockIdx.y * S_ + blockIdx.x) * J_;
    int tid = threadIdx.x;
    float4 v0 = *(const float4*)&row[tid * 8];
    float4 v1 = *(const float4*)&row[tid * 8 + 4];
    float m = fmaxf(fmaxf(fmaxf(v0.x, v0.y), fmaxf(v0.z, v0.w)),
                    fmaxf(fmaxf(v1.x, v1.y), fmaxf(v1.z, v1.w)));
    __shared__ float red[8];
#pragma unroll
    for (int o = 16; o > 0; o >>= 1) m = fmaxf(m, __shfl_xor_sync(0xffffffffu, m, o));
    if ((tid & 31) == 0) red[tid >> 5] = m;
    __syncthreads();
    m = red[0];
#pragma unroll
    for (int i = 1; i < 8; i++) m = fmaxf(m, red[i]);

    v0.x = __expf(v0.x - m); v0.y = __expf(v0.y - m);
    v0.z = __expf(v0.z - m); v0.w = __expf(v0.w - m);
    v1.x = __expf(v1.x - m); v1.y = __expf(v1.y - m);
    v1.z = __expf(v1.z - m); v1.w = __expf(v1.w - m);
    float s = v0.x + v0.y + v0.z + v0.w + v1.x + v1.y + v1.z + v1.w;
    __syncthreads();
#pragma unroll
    for (int o = 16; o > 0; o >>= 1) s += __shfl_xor_sync(0xffffffffu, s, o);
    if ((tid & 31) == 0) red[tid >> 5] = s;
    __syncthreads();
    s = 0.f;
#pragma unroll
    for (int i = 0; i < 8; i++) s += red[i];
    float inv = 1.0f / s;
    __nv_bfloat162 o0, o1, o2, o3;
    o0.x = __float2bfloat16(v0.x * inv); o0.y = __float2bfloat16(v0.y * inv);
    o1.x = __float2bfloat16(v0.z * inv); o1.y = __float2bfloat16(v0.w * inv);
    o2.x = __float2bfloat16(v1.x * inv); o2.y = __float2bfloat16(v1.y * inv);
    o3.x = __float2bfloat16(v1.z * inv); o3.y = __float2bfloat16(v1.w * inv);
    *(__nv_bfloat162*)&orow[tid * 8]     = o0;
    *(__nv_bfloat162*)&orow[tid * 8 + 2] = o1;
    *(__nv_bfloat162*)&orow[tid * 8 + 4] = o2;
    *(__nv_bfloat162*)&orow[tid * 8 + 6] = o3;
}

// ---------------- LayerNorm over E=1024 ------------------------------------
__global__ __launch_bounds__(256) void ln_kernel(const float* __restrict__ gamma,
                                                 const float* __restrict__ beta,
                                                 float* __restrict__ out) {
    int row = blockIdx.x;
    const float* x = g_o + (size_t)row * E_;
    int tid = threadIdx.x;
    float4 v = *(const float4*)&x[tid << 2];
    float s1 = v.x + v.y + v.z + v.w;
    float s2 = v.x * v.x + v.y * v.y + v.z * v.z + v.w * v.w;
    __shared__ float r1[8], r2[8];
#pragma unroll
    for (int o = 16; o > 0; o >>= 1) {
        s1 += __shfl_xor_sync(0xffffffffu, s1, o);
        s2 += __shfl_xor_sync(0xffffffffu, s2, o);
    }
    if ((tid & 31) == 0) { r1[tid >> 5] = s1; r2[tid >> 5] = s2; }
    __syncthreads();
    float S1 = 0.f, S2 = 0.f;
#pragma unroll
    for (int i = 0; i < 8; i++) { S1 += r1[i]; S2 += r2[i]; }
    float mean = S1 * (1.0f / E_);
    float var = S2 * (1.0f / E_) - mean * mean;
    float rstd = rsqrtf(var + 1e-5f);
    float4 g = *(const float4*)&gamma[tid << 2];
    float4 bb = *(const float4*)&beta[tid << 2];
    float4 o;
    o.x = (v.x - mean) * rstd * g.x + bb.x;
    o.y = (v.y - mean) * rstd * g.y + bb.y;
    o.z = (v.z - mean) * rstd * g.z + bb.z;
    o.w = (v.w - mean) * rstd * g.w + bb.w;
    *(float4*)&out[(size_t)row * E_ + (tid << 2)] = o;
}

// ---------------- launch ----------------------------------------------------
extern "C" void kernel_launch(void* const* d_in, const int* in_sizes, int n_in,
                              void* d_out, int out_size) {
    (void)in_sizes; (void)n_in; (void)out_size;
    const float* inputMHA = (const float*)d_in[0];
    const float* posEmb   = (const float*)d_in[1];
    const float* memory   = (const float*)d_in[2];
    const float* u        = (const float*)d_in[3];
    const float* v        = (const float*)d_in[4];
    const float* W_kv     = (const float*)d_in[6];
    const float* W_q      = (const float*)d_in[7];
    const float* W_p      = (const float*)d_in[8];
    const float* W_o      = (const float*)d_in[9];
    const float* gamma    = (const float*)d_in[10];
    const float* beta     = (const float*)d_in[11];

    float *pq, *pkv, *pp, *pawv, *po;
    cudaGetSymbolAddress((void**)&pq, g_q);
    cudaGetSymbolAddress((void**)&pkv, g_kv);
    cudaGetSymbolAddress((void**)&pp, g_p);
    cudaGetSymbolAddress((void**)&pawv, g_awv);
    cudaGetSymbolAddress((void**)&po, g_o);

    __nv_bfloat16 *xhi, *pehi, *ahi, *ppb;
    __nv_bfloat16 *wqh, *wql, *wkh, *wkl, *wph, *wpl, *woh, *wol;
    cudaGetSymbolAddress((void**)&xhi, g_xhi);
    cudaGetSymbolAddress((void**)&pehi, g_pehi);
    cudaGetSymbolAddress((void**)&ahi, g_ahi);
    cudaGetSymbolAddress((void**)&ppb, g_ppb);
    cudaGetSymbolAddress((void**)&wqh, g_wqhi);
    cudaGetSymbolAddress((void**)&wql, g_wqlo);
    cudaGetSymbolAddress((void**)&wkh, g_wkvhi);
    cudaGetSymbolAddress((void**)&wkl, g_wkvlo);
    cudaGetSymbolAddress((void**)&wph, g_wphi);
    cudaGetSymbolAddress((void**)&wpl, g_wplo);
    cudaGetSymbolAddress((void**)&woh, g_wohi);
    cudaGetSymbolAddress((void**)&wol, g_wolo);

    cudaFuncSetAttribute(hmma_gemm, cudaFuncAttributeMaxDynamicSharedMemorySize, GM_SMEM);
    cudaFuncSetAttribute(awv_hmma, cudaFuncAttributeMaxDynamicSharedMemorySize, AV_SMEM);
    cudaFuncSetAttribute(scores_hmma, cudaFuncAttributeMaxDynamicSharedMemorySize, SC_SMEM);

    // ---- convert inputs to bf16 ----
    cvt_kernel<<<4096, 256>>>(memory, xhi, P_ * B_ * E_);
    cvt_kernel<<<4096, 256>>>(inputMHA, xhi + (size_t)P_ * B_ * E_, S_ * B_ * E_);
    cvt_kernel<<<2048, 256>>>(posEmb, pehi, J_ * E_);
    tsplit_kernel<<<dim3(HI_ / 32, E_ / 32), dim3(32, 8)>>>(W_q, wqh, wql, E_, HI_);
    tsplit_kernel<<<dim3(2 * HI_ / 32, E_ / 32), dim3(32, 8)>>>(W_kv, wkh, wkl, E_, 2 * HI_);
    tsplit_kernel<<<dim3(HI_ / 32, E_ / 32), dim3(32, 8)>>>(W_p, wph, wpl, E_, HI_);
    tsplit_kernel<<<dim3(E_ / 32, HI_ / 32), dim3(32, 8)>>>(W_o, woh, wol, HI_, E_);

    // ---- linears (HMMA bf16x2) ----
    hmma_gemm<<<dim3(HI_ / 128, (S_ * B_) / 128), 256, GM_SMEM>>>(
        xhi + (size_t)P_ * B_ * E_, wqh, wql, nullptr, pq, S_ * B_, HI_, E_);
    hmma_gemm<<<dim3(2 * HI_ / 128, (J_ * B_) / 128), 256, GM_SMEM>>>(
        xhi, wkh, wkl, nullptr, pkv, J_ * B_, 2 * HI_, E_);
    hmma_gemm<<<dim3(HI_ / 128, J_ / 128), 256, GM_SMEM>>>(
        pehi, wph, wpl, nullptr, pp, J_, HI_, E_);

    // ---- bf16 operand prep for attention ----
    quv_kernel<<<4096, 256>>>(u, v);
    kb_kernel<<<8192, 256>>>();
    cvt_kernel<<<2048, 256>>>(pp, ppb, J_ * HI_);
    vt_kernel<<<dim3(J_ / 32, 2, B_ * H_), dim3(32, 8)>>>();

    // ---- attention ----
    scores_hmma<<<dim3(J_ / 64, S_ / 64, B_ * H_), 128, SC_SMEM>>>();
    softmax_kernel<<<dim3(S_, B_ * H_), 256>>>();
    awv_hmma<<<dim3(S_ / 128, B_ * H_), 256, AV_SMEM>>>();

    // ---- output projection + residual ----
    cvt_kernel<<<4096, 256>>>(pawv, ahi, S_ * B_ * HI_);
    hmma_gemm<<<dim3(E_ / 128, (S_ * B_) / 128), 256, GM_SMEM>>>(
        ahi, woh, wol, inputMHA, po, S_ * B_, E_, HI_);

    // ---- LayerNorm ----
    ln_kernel<<<S_ * B_, 256>>>(gamma, beta, (float*)d_out);
}

// round 16
// speedup vs baseline: 3.6949x; 1.2796x over previous
#include <cuda_runtime.h>
#include <cuda_bf16.h>
#include <cstdint>
#include <cstddef>

#define S_  1024
#define P_  1024
#define J_  2048
#define B_  4
#define E_  1024
#define H_  16
#define I_  64
#define HI_ 1024

// ---------------- fp32 scratch ----------------------------------------------
__device__ float g_q[(size_t)S_ * B_ * HI_];          // (S,B,H*I)
__device__ float g_kv[(size_t)J_ * B_ * 2 * HI_];     // (J,B,2*H*I)  keys | values
__device__ float g_p[(size_t)J_ * HI_];               // (J,H*I)
__device__ float g_o[(size_t)S_ * B_ * E_];           // pre-LN output
__device__ float g_duk[(size_t)B_ * H_ * J_];         // (u-v)·K per (bh, j)

// ---------------- bf16 scratch ----------------------------------------------
__device__ __nv_bfloat16 g_xhi[(size_t)8192 * 1024];   // [memory ; inputMHA] hi
__device__ __nv_bfloat16 g_pehi[(size_t)2048 * 1024];  // posEmb hi
__device__ __nv_bfloat16 g_ahi[(size_t)4096 * 1024];   // attention out bf16
__device__ __nv_bfloat16 g_vt[(size_t)B_ * H_ * 64 * J_];  // V^T per (b,h): [i][j]
__device__ __nv_bfloat16 g_qvb[(size_t)S_ * B_ * HI_];  // bf16(q+v)
__device__ __nv_bfloat16 g_kb[(size_t)J_ * B_ * HI_];   // keys bf16
__device__ __nv_bfloat16 g_ppb[(size_t)J_ * HI_];       // p bf16
__device__ __nv_bfloat16 g_wqhi[(size_t)1024 * 1024];  // W^T [N,K] hi/lo
__device__ __nv_bfloat16 g_wqlo[(size_t)1024 * 1024];
__device__ __nv_bfloat16 g_wkvhi[(size_t)2048 * 1024];
__device__ __nv_bfloat16 g_wkvlo[(size_t)2048 * 1024];
__device__ __nv_bfloat16 g_wphi[(size_t)1024 * 1024];
__device__ __nv_bfloat16 g_wplo[(size_t)1024 * 1024];
__device__ __nv_bfloat16 g_wohi[(size_t)1024 * 1024];
__device__ __nv_bfloat16 g_wolo[(size_t)1024 * 1024];

// ---------------- small helpers ---------------------------------------------
__device__ __forceinline__ uint32_t smem_u32(const void* p) {
    uint32_t a;
    asm("{ .reg .u64 t; cvta.to.shared.u64 t, %1; cvt.u32.u64 %0, t; }"
        : "=r"(a) : "l"(p));
    return a;
}
__device__ __forceinline__ void cpa16(uint32_t s, const void* g) {
    asm volatile("cp.async.cg.shared.global [%0], [%1], 16;" :: "r"(s), "l"(g));
}
__device__ __forceinline__ void cpa16z(uint32_t s, const void* g, int nbytes) {
    asm volatile("cp.async.cg.shared.global [%0], [%1], 16, %2;"
                 :: "r"(s), "l"(g), "r"(nbytes));
}
__device__ __forceinline__ void ldm_x4(uint32_t* d, uint32_t addr) {
    asm volatile("ldmatrix.sync.aligned.m8n8.x4.shared.b16 {%0,%1,%2,%3}, [%4];"
                 : "=r"(d[0]), "=r"(d[1]), "=r"(d[2]), "=r"(d[3]) : "r"(addr));
}
__device__ __forceinline__ void ldm_x2(uint32_t* d, uint32_t addr) {
    asm volatile("ldmatrix.sync.aligned.m8n8.x2.shared.b16 {%0,%1}, [%2];"
                 : "=r"(d[0]), "=r"(d[1]) : "r"(addr));
}
__device__ __forceinline__ void mma16816(float* c, const uint32_t* a, const uint32_t* b) {
    asm volatile("mma.sync.aligned.m16n8k16.row.col.f32.bf16.bf16.f32 "
                 "{%0,%1,%2,%3},{%4,%5,%6,%7},{%8,%9},{%0,%1,%2,%3};"
                 : "+f"(c[0]), "+f"(c[1]), "+f"(c[2]), "+f"(c[3])
                 : "r"(a[0]), "r"(a[1]), "r"(a[2]), "r"(a[3]), "r"(b[0]), "r"(b[1]));
}
__device__ __forceinline__ uint32_t pkbf2(float x, float y) {
    __nv_bfloat162 t;
    t.x = __float2bfloat16(x); t.y = __float2bfloat16(y);
    return *(uint32_t*)&t;
}

// ---------------- HMMA bf16x2 GEMM: C = A_hi*(B_hi+B_lo)^T (+res) -----------
#define ROWB   80
#define TILEB  (128 * ROWB)
#define STG    (3 * TILEB)
#define NSTG   3
#define GM_SMEM (NSTG * STG)

__device__ __forceinline__ void gload(uint32_t dst, const __nv_bfloat16* src,
                                      int row0, int ld, int k0, int tid) {
#pragma unroll
    for (int it = 0; it < 2; it++) {
        int idx = it * 256 + tid;
        int r = idx >> 2, c = idx & 3;
        cpa16(dst + r * ROWB + c * 16, src + (size_t)(row0 + r) * ld + k0 + c * 8);
    }
}

__global__ __launch_bounds__(256) void hmma_gemm(const __nv_bfloat16* __restrict__ Ahi,
                                                 const __nv_bfloat16* __restrict__ Bhi,
                                                 const __nv_bfloat16* __restrict__ Blo,
                                                 const float* __restrict__ res,
                                                 float* __restrict__ C,
                                                 int M, int N, int K) {
    extern __shared__ char smc[];
    uint32_t sb = smem_u32(smc);
    int tid = threadIdx.x, wid = tid >> 5, lane = tid & 31;
    int wm = wid & 1, wn = wid >> 1;
    int m0 = blockIdx.y * 128, n0 = blockIdx.x * 128;

    float acc[4][4][4];
#pragma unroll
    for (int t = 0; t < 4; t++)
#pragma unroll
        for (int s = 0; s < 4; s++)
#pragma unroll
            for (int r = 0; r < 4; r++) acc[t][s][r] = 0.f;

    const int NC = K / 32;
#pragma unroll
    for (int st = 0; st < 2; st++) {
        uint32_t base = sb + st * STG;
        gload(base,             Ahi, m0, K, st * 32, tid);
        gload(base + TILEB,     Bhi, n0, K, st * 32, tid);
        gload(base + 2 * TILEB, Blo, n0, K, st * 32, tid);
        asm volatile("cp.async.commit_group;" ::: "memory");
    }

    int a_row = (lane & 15), a_hi16 = (lane >> 4) * 16;
    int b_row = (lane & 7), b_hi16 = ((lane >> 3) & 1) * 16;

    for (int c = 0; c < NC; c++) {
        if (c + 2 < NC) {
            uint32_t base = sb + ((c + 2) % NSTG) * STG;
            gload(base,             Ahi, m0, K, (c + 2) * 32, tid);
            gload(base + TILEB,     Bhi, n0, K, (c + 2) * 32, tid);
            gload(base + 2 * TILEB, Blo, n0, K, (c + 2) * 32, tid);
        }
        asm volatile("cp.async.commit_group;" ::: "memory");
        asm volatile("cp.async.wait_group 2;" ::: "memory");
        __syncthreads();

        uint32_t base = sb + (c % NSTG) * STG;
        uint32_t aH = base, bH = base + TILEB, bL = base + 2 * TILEB;
#pragma unroll
        for (int kk = 0; kk < 2; kk++) {
            uint32_t ah[4][4], bh[4][2], bl[4][2];
#pragma unroll
            for (int t = 0; t < 4; t++) {
                uint32_t off = (uint32_t)((wm * 64 + t * 16 + a_row) * ROWB + kk * 32 + a_hi16);
                ldm_x4(ah[t], aH + off);
            }
#pragma unroll
            for (int s = 0; s < 4; s++) {
                uint32_t off = (uint32_t)((wn * 32 + s * 8 + b_row) * ROWB + kk * 32 + b_hi16);
                ldm_x2(bh[s], bH + off);
                ldm_x2(bl[s], bL + off);
            }
#pragma unroll
            for (int t = 0; t < 4; t++)
#pragma unroll
                for (int s = 0; s < 4; s++)
                    mma16816(acc[t][s], ah[t], bh[s]);
#pragma unroll
            for (int t = 0; t < 4; t++)
#pragma unroll
                for (int s = 0; s < 4; s++)
                    mma16816(acc[t][s], ah[t], bl[s]);
        }
        __syncthreads();
    }

#pragma unroll
    for (int t = 0; t < 4; t++) {
        int mg = m0 + wm * 64 + t * 16 + (lane >> 2);
#pragma unroll
        for (int s = 0; s < 4; s++) {
            int ng = n0 + wn * 32 + s * 8 + (lane & 3) * 2;
            float2 v0 = make_float2(acc[t][s][0], acc[t][s][1]);
            float2 v1 = make_float2(acc[t][s][2], acc[t][s][3]);
            if (res) {
                float2 r0 = *(const float2*)&res[(size_t)mg * N + ng];
                float2 r1 = *(const float2*)&res[(size_t)(mg + 8) * N + ng];
                v0.x += r0.x; v0.y += r0.y; v1.x += r1.x; v1.y += r1.y;
            }
            *(float2*)&C[(size_t)mg * N + ng] = v0;
            *(float2*)&C[(size_t)(mg + 8) * N + ng] = v1;
        }
    }
}

// ---------------- fused attention: scores + online softmax + P@V ------------
// CTA: 128 thr (4 warps), 64 s-rows for one (b,h); loop over 64-wide j tiles.
#define FB_ROW 144
#define FA_QV     0
#define FA_K(bf)  (9216 + (bf) * 9216)
#define FA_VT(bf) (27648 + (bf) * 9216)
#define FA_PW(sl) (46080 + (sl) * 9216)
#define FA_BT     73728
#define FA_DUK(bf) (107520 + (bf) * 256)
#define FA_SMEM   108032

__global__ __launch_bounds__(128, 2) void fused_attn() {
    int bh = blockIdx.y;
    int b = bh >> 4, h = bh & 15;
    int s0 = ((int)gridDim.x - 1 - (int)blockIdx.x) << 6;  // longest tiles first
    extern __shared__ char smc[];
    uint32_t sb = smem_u32(smc);
    float* Btf = (float*)(smc + FA_BT);
    int tid = threadIdx.x, wid = tid >> 5, lane = tid & 31;
    const int NT = (P_ + s0) / 64 + 1;

    int a_row = lane & 15, a_hi = (lane >> 4) * 16;
    int b_row = lane & 7, b_hi = ((lane >> 3) & 1) * 16;
    int m0w = wid * 16;
    int r1 = m0w + (lane >> 2), c0 = (lane & 3) * 2;

    // ---- prologue loads ----
    {
        const __nv_bfloat16* src = g_qvb + ((size_t)s0 * B_ + b) * HI_ + h * 64;
#pragma unroll
        for (int it = 0; it < 4; it++) {
            int idx = it * 128 + tid;
            int r = idx >> 3, ch = idx & 7;
            cpa16(sb + FA_QV + r * FB_ROW + ch * 16, src + (size_t)r * 4096 + ch * 8);
        }
    }
    const __nv_bfloat16* Ksrc = g_kb + (size_t)b * HI_ + h * 64;
    const __nv_bfloat16* Vsrc = g_vt + (size_t)bh * 64 * J_;
    const float* Dsrc = g_duk + (size_t)bh * J_;
#pragma unroll
    for (int it = 0; it < 4; it++) {       // K(0), VT(0)
        int idx = it * 128 + tid;
        int r = idx >> 3, ch = idx & 7;
        cpa16(sb + FA_K(0) + r * FB_ROW + ch * 16, Ksrc + (size_t)r * 4096 + ch * 8);
        cpa16(sb + FA_VT(0) + r * FB_ROW + ch * 16, Vsrc + (size_t)r * J_ + ch * 8);
    }
#pragma unroll
    for (int sl = 0; sl < 2; sl++) {       // PW slots 0,1 (tau=0,1)
        int dbase = sl * 64 - s0 + 960;
#pragma unroll
        for (int it = 0; it < 4; it++) {
            int idx = it * 128 + tid;
            int r = idx >> 3, ch = idx & 7;
            int d = dbase + r;
            int ok = ((unsigned)d < (unsigned)J_) ? 16 : 0;
            int dc = d < 0 ? 0 : (d >= J_ ? J_ - 1 : d);
            cpa16z(sb + FA_PW(sl) + r * FB_ROW + ch * 16,
                   g_ppb + (size_t)dc * HI_ + h * 64 + ch * 8, ok);
        }
    }
    if (tid < 16) cpa16(sb + FA_DUK(0) + tid * 16, Dsrc + tid * 4);
    asm volatile("cp.async.commit_group;" ::: "memory");
    asm volatile("cp.async.wait_group 0;" ::: "memory");
    __syncthreads();

    // QV fragments (A operand for both pos and content) — loaded once
    uint32_t af[4][4];
#pragma unroll
    for (int kk = 0; kk < 4; kk++)
        ldm_x4(af[kk], sb + FA_QV + (m0w + a_row) * FB_ROW + kk * 32 + a_hi);

    float m1 = -1e30f, m2 = -1e30f, l1 = 0.f, l2 = 0.f;
    float O[8][4];
#pragma unroll
    for (int g = 0; g < 8; g++)
#pragma unroll
        for (int r = 0; r < 4; r++) O[g][r] = 0.f;

    for (int t = 0; t < NT; t++) {
        // ---- prefetch t+1 (K/VT/duk) and p-block tau=t+2 ----
        if (t + 1 < NT) {
            int nb = (t + 1) & 1, j1 = (t + 1) * 64;
#pragma unroll
            for (int it = 0; it < 4; it++) {
                int idx = it * 128 + tid;
                int r = idx >> 3, ch = idx & 7;
                cpa16(sb + FA_K(nb) + r * FB_ROW + ch * 16,
                      Ksrc + (size_t)(j1 + r) * 4096 + ch * 8);
                cpa16(sb + FA_VT(nb) + r * FB_ROW + ch * 16,
                      Vsrc + (size_t)r * J_ + j1 + ch * 8);
            }
            int dbase = (t + 2) * 64 - s0 + 960;
            int sl = (t + 2) % 3;
#pragma unroll
            for (int it = 0; it < 4; it++) {
                int idx = it * 128 + tid;
                int r = idx >> 3, ch = idx & 7;
                int d = dbase + r;
                int ok = ((unsigned)d < (unsigned)J_) ? 16 : 0;
                int dc = d < 0 ? 0 : (d >= J_ ? J_ - 1 : d);
                cpa16z(sb + FA_PW(sl) + r * FB_ROW + ch * 16,
                       g_ppb + (size_t)dc * HI_ + h * 64 + ch * 8, ok);
            }
            if (tid < 16) cpa16(sb + FA_DUK(nb) + tid * 16, Dsrc + j1 + tid * 4);
            asm volatile("cp.async.commit_group;" ::: "memory");
        }

        int cur = t & 1, j0 = t * 64;
        uint32_t pwA = sb + FA_PW(t % 3), pwB = sb + FA_PW((t + 1) % 3);
        const float* duk_s = (const float*)(smc + FA_DUK(cur));

        // ---- pos scores -> Bt[64 x 128] (each warp its 16 rows) ----
#pragma unroll
        for (int n = 0; n < 16; n++) {
            float ac[4] = {0.f, 0.f, 0.f, 0.f};
            uint32_t base = (n < 8) ? pwA : pwB;
            uint32_t roff = (uint32_t)(((n & 7) * 8 + b_row) * FB_ROW);
#pragma unroll
            for (int kk = 0; kk < 4; kk++) {
                uint32_t bf[2];
                ldm_x2(bf, base + roff + kk * 32 + b_hi);
                mma16816(ac, af[kk], bf);
            }
            *(float2*)&Btf[r1 * 132 + n * 8 + c0] = make_float2(ac[0], ac[1]);
            *(float2*)&Btf[(r1 + 8) * 132 + n * 8 + c0] = make_float2(ac[2], ac[3]);
        }
        __syncwarp();

        // ---- content scores ----
        float lg[8][4];
#pragma unroll
        for (int n = 0; n < 8; n++) {
            float ac[4] = {0.f, 0.f, 0.f, 0.f};
            uint32_t roff = (uint32_t)((n * 8 + b_row) * FB_ROW);
#pragma unroll
            for (int kk = 0; kk < 4; kk++) {
                uint32_t bf[2];
                ldm_x2(bf, sb + FA_K(cur) + roff + kk * 32 + b_hi);
                mma16816(ac, af[kk], bf);
            }
            lg[n][0] = ac[0]; lg[n][1] = ac[1]; lg[n][2] = ac[2]; lg[n][3] = ac[3];
        }

        // ---- combine: + duk + shifted pos, scale, mask ----
        int lim1 = P_ + s0 + r1 - j0;
        int lim2 = lim1 + 8;
        int r2 = r1 + 8;
#pragma unroll
        for (int n = 0; n < 8; n++) {
            int c = n * 8 + c0;
            float d0v = duk_s[c], d1v = duk_s[c + 1];
            float v00 = (lg[n][0] + d0v + Btf[r1 * 132 + (c - r1 + 63)]) * 0.125f;
            float v01 = (lg[n][1] + d1v + Btf[r1 * 132 + (c + 1 - r1 + 63)]) * 0.125f;
            float v10 = (lg[n][2] + d0v + Btf[r2 * 132 + (c - r2 + 63)]) * 0.125f;
            float v11 = (lg[n][3] + d1v + Btf[r2 * 132 + (c + 1 - r2 + 63)]) * 0.125f;
            lg[n][0] = (c     <= lim1) ? v00 : -1e30f;
            lg[n][1] = (c + 1 <= lim1) ? v01 : -1e30f;
            lg[n][2] = (c     <= lim2) ? v10 : -1e30f;
            lg[n][3] = (c + 1 <= lim2) ? v11 : -1e30f;
        }

        // ---- online softmax ----
        float rx1 = -1e30f, rx2 = -1e30f;
#pragma unroll
        for (int n = 0; n < 8; n++) {
            rx1 = fmaxf(rx1, fmaxf(lg[n][0], lg[n][1]));
            rx2 = fmaxf(rx2, fmaxf(lg[n][2], lg[n][3]));
        }
#pragma unroll
        for (int o = 1; o < 4; o <<= 1) {
            rx1 = fmaxf(rx1, __shfl_xor_sync(0xffffffffu, rx1, o));
            rx2 = fmaxf(rx2, __shfl_xor_sync(0xffffffffu, rx2, o));
        }
        float m1n = fmaxf(m1, rx1), m2n = fmaxf(m2, rx2);
        float sc1 = __expf(m1 - m1n), sc2 = __expf(m2 - m2n);
        m1 = m1n; m2 = m2n;
        float rs1 = 0.f, rs2 = 0.f;
#pragma unroll
        for (int n = 0; n < 8; n++) {
            lg[n][0] = __expf(lg[n][0] - m1); rs1 += lg[n][0];
            lg[n][1] = __expf(lg[n][1] - m1); rs1 += lg[n][1];
            lg[n][2] = __expf(lg[n][2] - m2); rs2 += lg[n][2];
            lg[n][3] = __expf(lg[n][3] - m2); rs2 += lg[n][3];
        }
#pragma unroll
        for (int o = 1; o < 4; o <<= 1) {
            rs1 += __shfl_xor_sync(0xffffffffu, rs1, o);
            rs2 += __shfl_xor_sync(0xffffffffu, rs2, o);
        }
        l1 = l1 * sc1 + rs1;
        l2 = l2 * sc2 + rs2;
#pragma unroll
        for (int g = 0; g < 8; g++) {
            O[g][0] *= sc1; O[g][1] *= sc1; O[g][2] *= sc2; O[g][3] *= sc2;
        }

        // ---- P @ V (D-fragment == A-fragment identity) ----
#pragma unroll
        for (int kb = 0; kb < 4; kb++) {
            uint32_t pa[4];
            pa[0] = pkbf2(lg[2 * kb][0], lg[2 * kb][1]);
            pa[1] = pkbf2(lg[2 * kb][2], lg[2 * kb][3]);
            pa[2] = pkbf2(lg[2 * kb + 1][0], lg[2 * kb + 1][1]);
            pa[3] = pkbf2(lg[2 * kb + 1][2], lg[2 * kb + 1][3]);
#pragma unroll
            for (int n2 = 0; n2 < 8; n2++) {
                uint32_t bv[2];
                ldm_x2(bv, sb + FA_VT(cur) + (uint32_t)((n2 * 8 + b_row) * FB_ROW) + kb * 32 + b_hi);
                mma16816(O[n2], pa, bv);
            }
        }

        asm volatile("cp.async.wait_group 0;" ::: "memory");
        __syncthreads();
    }

    // ---- epilogue: normalize, write bf16 ----
    float inv1 = 1.f / l1, inv2 = 1.f / l2;
    __nv_bfloat16* d1 = g_ahi + ((size_t)(s0 + r1) * B_ + b) * HI_ + h * 64;
    __nv_bfloat16* d2 = g_ahi + ((size_t)(s0 + r1 + 8) * B_ + b) * HI_ + h * 64;
#pragma unroll
    for (int g = 0; g < 8; g++) {
        *(uint32_t*)(d1 + g * 8 + c0) = pkbf2(O[g][0] * inv1, O[g][1] * inv1);
        *(uint32_t*)(d2 + g * 8 + c0) = pkbf2(O[g][2] * inv2, O[g][3] * inv2);
    }
}

// ---------------- fp32 -> bf16 (hi only) ------------------------------------
__global__ __launch_bounds__(256) void cvt_kernel(const float* __restrict__ x,
                                                  __nv_bfloat16* __restrict__ hi,
                                                  int n) {
    int i = (blockIdx.x * 256 + threadIdx.x) * 4;
    if (i >= n) return;
    float4 v = *(const float4*)&x[i];
    __nv_bfloat162 h0, h1;
    h0.x = __float2bfloat16(v.x); h0.y = __float2bfloat16(v.y);
    h1.x = __float2bfloat16(v.z); h1.y = __float2bfloat16(v.w);
    *(__nv_bfloat162*)&hi[i] = h0;
    *(__nv_bfloat162*)&hi[i + 2] = h1;
}

// ---------------- qv = bf16(q + v) ------------------------------------------
__global__ __launch_bounds__(256) void quv_kernel(const float* __restrict__ v) {
    int i = (blockIdx.x * 256 + threadIdx.x) * 4;
    float4 q = *(const float4*)&g_q[i];
    int x = i & (HI_ - 1);
    float4 v4 = *(const float4*)&v[x];
    __nv_bfloat162 b0, b1;
    b0.x = __float2bfloat16(q.x + v4.x); b0.y = __float2bfloat16(q.y + v4.y);
    b1.x = __float2bfloat16(q.z + v4.z); b1.y = __float2bfloat16(q.w + v4.w);
    *(__nv_bfloat162*)&g_qvb[i] = b0;
    *(__nv_bfloat162*)&g_qvb[i + 2] = b1;
}

// ---------------- keys -> bf16 [J,B,HI] -------------------------------------
__global__ __launch_bounds__(256) void kb_kernel() {
    int i = (blockIdx.x * 256 + threadIdx.x) * 4;
    int row = i >> 10, x = i & (HI_ - 1);
    float4 k = *(const float4*)&g_kv[((size_t)row << 11) + x];
    __nv_bfloat162 h0, h1;
    h0.x = __float2bfloat16(k.x); h0.y = __float2bfloat16(k.y);
    h1.x = __float2bfloat16(k.z); h1.y = __float2bfloat16(k.w);
    *(__nv_bfloat162*)&g_kb[i] = h0;
    *(__nv_bfloat162*)&g_kb[i + 2] = h1;
}

// ---------------- duk[bh][j] = (u - v) · K_bf16[j,b,h,:] --------------------
__global__ __launch_bounds__(256) void duk_kernel(const float* __restrict__ u,
                                                  const float* __restrict__ v) {
    int id = blockIdx.x * 256 + threadIdx.x;   // bh * J + j
    int bh = id >> 11, j = id & (J_ - 1);
    int b = bh >> 4, h = bh & 15;
    const __nv_bfloat16* kp = g_kb + ((size_t)j * B_ + b) * HI_ + h * 64;
    float s = 0.f;
#pragma unroll
    for (int i = 0; i < 64; i += 2) {
        __nv_bfloat162 k2 = *(const __nv_bfloat162*)&kp[i];
        s += (u[h * 64 + i] - v[h * 64 + i]) * __bfloat162float(k2.x);
        s += (u[h * 64 + i + 1] - v[h * 64 + i + 1]) * __bfloat162float(k2.y);
    }
    g_duk[id] = s;
}

// ---------------- W[K,N] -> T[N,K] transpose + hi/lo split ------------------
__global__ void tsplit_kernel(const float* __restrict__ W,
                              __nv_bfloat16* __restrict__ Thi,
                              __nv_bfloat16* __restrict__ Tlo,
                              int Kd, int Nd) {
    __shared__ float t[32][33];
    int n0 = blockIdx.x * 32, k0 = blockIdx.y * 32;
    int tx = threadIdx.x, ty = threadIdx.y;
#pragma unroll
    for (int r = 0; r < 32; r += 8)
        t[ty + r][tx] = W[(size_t)(k0 + ty + r) * Nd + n0 + tx];
    __syncthreads();
#pragma unroll
    for (int r = 0; r < 32; r += 8) {
        float v = t[tx][ty + r];
        __nv_bfloat16 h = __float2bfloat16(v);
        Thi[(size_t)(n0 + ty + r) * Kd + k0 + tx] = h;
        Tlo[(size_t)(n0 + ty + r) * Kd + k0 + tx] =
            __float2bfloat16(v - __bfloat162float(h));
    }
}

// ---------------- values -> V^T bf16 per (b,h): [i][j] ----------------------
__global__ void vt_kernel() {
    __shared__ float t[32][33];
    int j0 = blockIdx.x * 32, i0 = blockIdx.y * 32;
    int bh = blockIdx.z;
    int b = bh >> 4, h = bh & 15;
    int tx = threadIdx.x, ty = threadIdx.y;
#pragma unroll
    for (int r = 0; r < 32; r += 8)
        t[ty + r][tx] = g_kv[((size_t)(j0 + ty + r) * B_ + b) * (2 * HI_) + HI_ + h * 64 + i0 + tx];
    __syncthreads();
#pragma unroll
    for (int r = 0; r < 32; r += 8)
        g_vt[((size_t)bh * 64 + i0 + ty + r) * J_ + j0 + tx] =
            __float2bfloat16(t[tx][ty + r]);
}

// ---------------- LayerNorm over E=1024 ------------------------------------
__global__ __launch_bounds__(256) void ln_kernel(const float* __restrict__ gamma,
                                                 const float* __restrict__ beta,
                                                 float* __restrict__ out) {
    int row = blockIdx.x;
    const float* x = g_o + (size_t)row * E_;
    int tid = threadIdx.x;
    float4 v = *(const float4*)&x[tid << 2];
    float s1 = v.x + v.y + v.z + v.w;
    float s2 = v.x * v.x + v.y * v.y + v.z * v.z + v.w * v.w;
    __shared__ float r1[8], r2[8];
#pragma unroll
    for (int o = 16; o > 0; o >>= 1) {
        s1 += __shfl_xor_sync(0xffffffffu, s1, o);
        s2 += __shfl_xor_sync(0xffffffffu, s2, o);
    }
    if ((tid & 31) == 0) { r1[tid >> 5] = s1; r2[tid >> 5] = s2; }
    __syncthreads();
    float S1 = 0.f, S2 = 0.f;
#pragma unroll
    for (int i = 0; i < 8; i++) { S1 += r1[i]; S2 += r2[i]; }
    float mean = S1 * (1.0f / E_);
    float var = S2 * (1.0f / E_) - mean * mean;
    float rstd = rsqrtf(var + 1e-5f);
    float4 g = *(const float4*)&gamma[tid << 2];
    float4 bb = *(const float4*)&beta[tid << 2];
    float4 o;
    o.x = (v.x - mean) * rstd * g.x + bb.x;
    o.y = (v.y - mean) * rstd * g.y + bb.y;
    o.z = (v.z - mean) * rstd * g.z + bb.z;
    o.w = (v.w - mean) * rstd * g.w + bb.w;
    *(float4*)&out[(size_t)row * E_ + (tid << 2)] = o;
}

// ---------------- launch ----------------------------------------------------
extern "C" void kernel_launch(void* const* d_in, const int* in_sizes, int n_in,
                              void* d_out, int out_size) {
    (void)in_sizes; (void)n_in; (void)out_size;
    const float* inputMHA = (const float*)d_in[0];
    const float* posEmb   = (const float*)d_in[1];
    const float* memory   = (const float*)d_in[2];
    const float* u        = (const float*)d_in[3];
    const float* v        = (const float*)d_in[4];
    const float* W_kv     = (const float*)d_in[6];
    const float* W_q      = (const float*)d_in[7];
    const float* W_p      = (const float*)d_in[8];
    const float* W_o      = (const float*)d_in[9];
    const float* gamma    = (const float*)d_in[10];
    const float* beta     = (const float*)d_in[11];

    float *pq, *pkv, *pp, *po;
    cudaGetSymbolAddress((void**)&pq, g_q);
    cudaGetSymbolAddress((void**)&pkv, g_kv);
    cudaGetSymbolAddress((void**)&pp, g_p);
    cudaGetSymbolAddress((void**)&po, g_o);

    __nv_bfloat16 *xhi, *pehi, *ahi, *ppb;
    __nv_bfloat16 *wqh, *wql, *wkh, *wkl, *wph, *wpl, *woh, *wol;
    cudaGetSymbolAddress((void**)&xhi, g_xhi);
    cudaGetSymbolAddress((void**)&pehi, g_pehi);
    cudaGetSymbolAddress((void**)&ahi, g_ahi);
    cudaGetSymbolAddress((void**)&ppb, g_ppb);
    cudaGetSymbolAddress((void**)&wqh, g_wqhi);
    cudaGetSymbolAddress((void**)&wql, g_wqlo);
    cudaGetSymbolAddress((void**)&wkh, g_wkvhi);
    cudaGetSymbolAddress((void**)&wkl, g_wkvlo);
    cudaGetSymbolAddress((void**)&wph, g_wphi);
    cudaGetSymbolAddress((void**)&wpl, g_wplo);
    cudaGetSymbolAddress((void**)&woh, g_wohi);
    cudaGetSymbolAddress((void**)&wol, g_wolo);

    cudaFuncSetAttribute(hmma_gemm, cudaFuncAttributeMaxDynamicSharedMemorySize, GM_SMEM);
    cudaFuncSetAttribute(fused_attn, cudaFuncAttributeMaxDynamicSharedMemorySize, FA_SMEM);

    // ---- convert inputs to bf16 ----
    cvt_kernel<<<4096, 256>>>(memory, xhi, P_ * B_ * E_);
    cvt_kernel<<<4096, 256>>>(inputMHA, xhi + (size_t)P_ * B_ * E_, S_ * B_ * E_);
    cvt_kernel<<<2048, 256>>>(posEmb, pehi, J_ * E_);
    tsplit_kernel<<<dim3(HI_ / 32, E_ / 32), dim3(32, 8)>>>(W_q, wqh, wql, E_, HI_);
    tsplit_kernel<<<dim3(2 * HI_ / 32, E_ / 32), dim3(32, 8)>>>(W_kv, wkh, wkl, E_, 2 * HI_);
    tsplit_kernel<<<dim3(HI_ / 32, E_ / 32), dim3(32, 8)>>>(W_p, wph, wpl, E_, HI_);
    tsplit_kernel<<<dim3(E_ / 32, HI_ / 32), dim3(32, 8)>>>(W_o, woh, wol, HI_, E_);

    // ---- linears (HMMA bf16x2) ----
    hmma_gemm<<<dim3(HI_ / 128, (S_ * B_) / 128), 256, GM_SMEM>>>(
        xhi + (size_t)P_ * B_ * E_, wqh, wql, nullptr, pq, S_ * B_, HI_, E_);
    hmma_gemm<<<dim3(2 * HI_ / 128, (J_ * B_) / 128), 256, GM_SMEM>>>(
        xhi, wkh, wkl, nullptr, pkv, J_ * B_, 2 * HI_, E_);
    hmma_gemm<<<dim3(HI_ / 128, J_ / 128), 256, GM_SMEM>>>(
        pehi, wph, wpl, nullptr, pp, J_, HI_, E_);

    // ---- bf16 operand prep for fused attention ----
    quv_kernel<<<4096, 256>>>(v);
    kb_kernel<<<8192, 256>>>();
    cvt_kernel<<<2048, 256>>>(pp, ppb, J_ * HI_);
    vt_kernel<<<dim3(J_ / 32, 2, B_ * H_), dim3(32, 8)>>>();
    duk_kernel<<<(B_ * H_ * J_) / 256, 256>>>(u, v);

    // ---- fused attention (scores + softmax + P@V) -> g_ahi ----
    fused_attn<<<dim3(S_ / 64, B_ * H_), 128, FA_SMEM>>>();

    // ---- output projection + residual ----
    hmma_gemm<<<dim3(E_ / 128, (S_ * B_) / 128), 256, GM_SMEM>>>(
        ahi, woh, wol, inputMHA, po, S_ * B_, E_, HI_);

    // ---- LayerNorm ----
    ln_kernel<<<S_ * B_, 256>>>(gamma, beta, (float*)d_out);
}

// round 17
// speedup vs baseline: 4.8064x; 1.3008x over previous
#include <cuda_runtime.h>
#include <cuda_fp16.h>
#include <cstdint>
#include <cstddef>

#define S_  1024
#define P_  1024
#define J_  2048
#define B_  4
#define E_  1024
#define H_  16
#define I_  64
#define HI_ 1024

// ---------------- fp32 scratch ----------------------------------------------
__device__ float g_o[(size_t)S_ * B_ * E_];           // pre-LN output
__device__ float g_duk[(size_t)B_ * H_ * J_];         // (u-v)·K per (bh, j)

// ---------------- fp16 scratch ----------------------------------------------
__device__ __half g_xh[(size_t)8192 * 1024];    // [memory ; inputMHA]
__device__ __half g_peh[(size_t)2048 * 1024];   // posEmb
__device__ __half g_ahh[(size_t)4096 * 1024];   // attention out
__device__ __half g_vth[(size_t)B_ * H_ * 64 * J_];  // V^T per (b,h): [i][j]
__device__ __half g_qvh[(size_t)S_ * B_ * HI_]; // q + v
__device__ __half g_kvh[(size_t)8192 * 2048];   // kv projection (keys|values)
__device__ __half g_pph[(size_t)J_ * HI_];      // p
__device__ __half g_wqh[(size_t)1024 * 1024];   // W^T [N,K]
__device__ __half g_wkvh[(size_t)2048 * 1024];
__device__ __half g_wph[(size_t)1024 * 1024];
__device__ __half g_woh[(size_t)1024 * 1024];

// ---------------- small helpers ---------------------------------------------
__device__ __forceinline__ uint32_t smem_u32(const void* p) {
    uint32_t a;
    asm("{ .reg .u64 t; cvta.to.shared.u64 t, %1; cvt.u32.u64 %0, t; }"
        : "=r"(a) : "l"(p));
    return a;
}
__device__ __forceinline__ void cpa16(uint32_t s, const void* g) {
    asm volatile("cp.async.cg.shared.global [%0], [%1], 16;" :: "r"(s), "l"(g));
}
__device__ __forceinline__ void cpa16z(uint32_t s, const void* g, int nbytes) {
    asm volatile("cp.async.cg.shared.global [%0], [%1], 16, %2;"
                 :: "r"(s), "l"(g), "r"(nbytes));
}
__device__ __forceinline__ void ldm_x4(uint32_t* d, uint32_t addr) {
    asm volatile("ldmatrix.sync.aligned.m8n8.x4.shared.b16 {%0,%1,%2,%3}, [%4];"
                 : "=r"(d[0]), "=r"(d[1]), "=r"(d[2]), "=r"(d[3]) : "r"(addr));
}
__device__ __forceinline__ void ldm_x2(uint32_t* d, uint32_t addr) {
    asm volatile("ldmatrix.sync.aligned.m8n8.x2.shared.b16 {%0,%1}, [%2];"
                 : "=r"(d[0]), "=r"(d[1]) : "r"(addr));
}
__device__ __forceinline__ void mma16816(float* c, const uint32_t* a, const uint32_t* b) {
    asm volatile("mma.sync.aligned.m16n8k16.row.col.f32.f16.f16.f32 "
                 "{%0,%1,%2,%3},{%4,%5,%6,%7},{%8,%9},{%0,%1,%2,%3};"
                 : "+f"(c[0]), "+f"(c[1]), "+f"(c[2]), "+f"(c[3])
                 : "r"(a[0]), "r"(a[1]), "r"(a[2]), "r"(a[3]), "r"(b[0]), "r"(b[1]));
}
__device__ __forceinline__ uint32_t pkhf2(float x, float y) {
    __half2 t = __floats2half2_rn(x, y);
    return *(uint32_t*)&t;
}

// ---------------- HMMA fp16 x1 GEMM: C[M,N] = A[M,K]*B[N,K]^T ---------------
// Outputs: optional fp32 (+res) and/or fp16 (+bias[n]).
#define ROWB   80
#define TILEB  (128 * ROWB)
#define STG    (2 * TILEB)    // A + B per stage = 20480
#define NSTG   3
#define GM_SMEM (NSTG * STG)  // 61440

__device__ __forceinline__ void gload(uint32_t dst, const __half* src,
                                      int row0, int ld, int k0, int tid) {
#pragma unroll
    for (int it = 0; it < 2; it++) {
        int idx = it * 256 + tid;
        int r = idx >> 2, c = idx & 3;
        cpa16(dst + r * ROWB + c * 16, src + (size_t)(row0 + r) * ld + k0 + c * 8);
    }
}

__global__ __launch_bounds__(256) void hmma_gemm(const __half* __restrict__ Ah,
                                                 const __half* __restrict__ Bh,
                                                 const float* __restrict__ res,
                                                 float* __restrict__ C,
                                                 __half* __restrict__ Ch,
                                                 const float* __restrict__ bias,
                                                 int M, int N, int K) {
    extern __shared__ char smc[];
    uint32_t sb = smem_u32(smc);
    int tid = threadIdx.x, wid = tid >> 5, lane = tid & 31;
    int wm = wid & 1, wn = wid >> 1;
    int m0 = blockIdx.y * 128, n0 = blockIdx.x * 128;

    float acc[4][4][4];
#pragma unroll
    for (int t = 0; t < 4; t++)
#pragma unroll
        for (int s = 0; s < 4; s++)
#pragma unroll
            for (int r = 0; r < 4; r++) acc[t][s][r] = 0.f;

    const int NC = K / 32;
#pragma unroll
    for (int st = 0; st < 2; st++) {
        uint32_t base = sb + st * STG;
        gload(base,         Ah, m0, K, st * 32, tid);
        gload(base + TILEB, Bh, n0, K, st * 32, tid);
        asm volatile("cp.async.commit_group;" ::: "memory");
    }

    int a_row = (lane & 15), a_hi16 = (lane >> 4) * 16;
    int b_row = (lane & 7), b_hi16 = ((lane >> 3) & 1) * 16;

    for (int c = 0; c < NC; c++) {
        if (c + 2 < NC) {
            uint32_t base = sb + ((c + 2) % NSTG) * STG;
            gload(base,         Ah, m0, K, (c + 2) * 32, tid);
            gload(base + TILEB, Bh, n0, K, (c + 2) * 32, tid);
        }
        asm volatile("cp.async.commit_group;" ::: "memory");
        asm volatile("cp.async.wait_group 2;" ::: "memory");
        __syncthreads();

        uint32_t base = sb + (c % NSTG) * STG;
        uint32_t aH = base, bH = base + TILEB;
#pragma unroll
        for (int kk = 0; kk < 2; kk++) {
            uint32_t ah[4][4], bh[4][2];
#pragma unroll
            for (int t = 0; t < 4; t++) {
                uint32_t off = (uint32_t)((wm * 64 + t * 16 + a_row) * ROWB + kk * 32 + a_hi16);
                ldm_x4(ah[t], aH + off);
            }
#pragma unroll
            for (int s = 0; s < 4; s++) {
                uint32_t off = (uint32_t)((wn * 32 + s * 8 + b_row) * ROWB + kk * 32 + b_hi16);
                ldm_x2(bh[s], bH + off);
            }
#pragma unroll
            for (int t = 0; t < 4; t++)
#pragma unroll
                for (int s = 0; s < 4; s++)
                    mma16816(acc[t][s], ah[t], bh[s]);
        }
        __syncthreads();
    }

#pragma unroll
    for (int t = 0; t < 4; t++) {
        int mg = m0 + wm * 64 + t * 16 + (lane >> 2);
#pragma unroll
        for (int s = 0; s < 4; s++) {
            int ng = n0 + wn * 32 + s * 8 + (lane & 3) * 2;
            float2 v0 = make_float2(acc[t][s][0], acc[t][s][1]);
            float2 v1 = make_float2(acc[t][s][2], acc[t][s][3]);
            if (res) {
                float2 r0 = *(const float2*)&res[(size_t)mg * N + ng];
                float2 r1 = *(const float2*)&res[(size_t)(mg + 8) * N + ng];
                v0.x += r0.x; v0.y += r0.y; v1.x += r1.x; v1.y += r1.y;
            }
            if (bias) {
                float b0 = bias[ng], b1 = bias[ng + 1];
                v0.x += b0; v0.y += b1; v1.x += b0; v1.y += b1;
            }
            if (C) {
                *(float2*)&C[(size_t)mg * N + ng] = v0;
                *(float2*)&C[(size_t)(mg + 8) * N + ng] = v1;
            }
            if (Ch) {
                *(uint32_t*)&Ch[(size_t)mg * N + ng] = pkhf2(v0.x, v0.y);
                *(uint32_t*)&Ch[(size_t)(mg + 8) * N + ng] = pkhf2(v1.x, v1.y);
            }
        }
    }
}

// ---------------- fused attention: scores + online softmax + P@V ------------
#define FB_ROW 144
#define FA_QV     0
#define FA_K(bf)  (9216 + (bf) * 9216)
#define FA_VT(bf) (27648 + (bf) * 9216)
#define FA_PW(sl) (46080 + (sl) * 9216)
#define FA_BT     73728
#define FA_DUK(bf) (107520 + (bf) * 256)
#define FA_SMEM   108032

__global__ __launch_bounds__(128, 2) void fused_attn() {
    int bh = blockIdx.y;
    int b = bh >> 4, h = bh & 15;
    int s0 = ((int)gridDim.x - 1 - (int)blockIdx.x) << 6;  // longest tiles first
    extern __shared__ char smc[];
    uint32_t sb = smem_u32(smc);
    float* Btf = (float*)(smc + FA_BT);
    int tid = threadIdx.x, wid = tid >> 5, lane = tid & 31;
    const int NT = (P_ + s0) / 64 + 1;

    int a_row = lane & 15, a_hi = (lane >> 4) * 16;
    int b_row = lane & 7, b_hi = ((lane >> 3) & 1) * 16;
    int m0w = wid * 16;
    int r1 = m0w + (lane >> 2), c0 = (lane & 3) * 2;

    // ---- prologue loads ----
    {
        const __half* src = g_qvh + ((size_t)s0 * B_ + b) * HI_ + h * 64;
#pragma unroll
        for (int it = 0; it < 4; it++) {
            int idx = it * 128 + tid;
            int r = idx >> 3, ch = idx & 7;
            cpa16(sb + FA_QV + r * FB_ROW + ch * 16, src + (size_t)r * 4096 + ch * 8);
        }
    }
    const __half* Ksrc = g_kvh + (size_t)b * 2048 + h * 64;   // row stride 8192
    const __half* Vsrc = g_vth + (size_t)bh * 64 * J_;
    const float* Dsrc = g_duk + (size_t)bh * J_;
#pragma unroll
    for (int it = 0; it < 4; it++) {       // K(0), VT(0)
        int idx = it * 128 + tid;
        int r = idx >> 3, ch = idx & 7;
        cpa16(sb + FA_K(0) + r * FB_ROW + ch * 16, Ksrc + (size_t)r * 8192 + ch * 8);
        cpa16(sb + FA_VT(0) + r * FB_ROW + ch * 16, Vsrc + (size_t)r * J_ + ch * 8);
    }
#pragma unroll
    for (int sl = 0; sl < 2; sl++) {       // PW slots 0,1
        int dbase = sl * 64 - s0 + 960;
#pragma unroll
        for (int it = 0; it < 4; it++) {
            int idx = it * 128 + tid;
            int r = idx >> 3, ch = idx & 7;
            int d = dbase + r;
            int ok = ((unsigned)d < (unsigned)J_) ? 16 : 0;
            int dc = d < 0 ? 0 : (d >= J_ ? J_ - 1 : d);
            cpa16z(sb + FA_PW(sl) + r * FB_ROW + ch * 16,
                   g_pph + (size_t)dc * HI_ + h * 64 + ch * 8, ok);
        }
    }
    if (tid < 16) cpa16(sb + FA_DUK(0) + tid * 16, Dsrc + tid * 4);
    asm volatile("cp.async.commit_group;" ::: "memory");
    asm volatile("cp.async.wait_group 0;" ::: "memory");
    __syncthreads();

    uint32_t af[4][4];
#pragma unroll
    for (int kk = 0; kk < 4; kk++)
        ldm_x4(af[kk], sb + FA_QV + (m0w + a_row) * FB_ROW + kk * 32 + a_hi);

    float m1 = -1e30f, m2 = -1e30f, l1 = 0.f, l2 = 0.f;
    float O[8][4];
#pragma unroll
    for (int g = 0; g < 8; g++)
#pragma unroll
        for (int r = 0; r < 4; r++) O[g][r] = 0.f;

    for (int t = 0; t < NT; t++) {
        if (t + 1 < NT) {
            int nb = (t + 1) & 1, j1 = (t + 1) * 64;
#pragma unroll
            for (int it = 0; it < 4; it++) {
                int idx = it * 128 + tid;
                int r = idx >> 3, ch = idx & 7;
                cpa16(sb + FA_K(nb) + r * FB_ROW + ch * 16,
                      Ksrc + (size_t)(j1 + r) * 8192 + ch * 8);
                cpa16(sb + FA_VT(nb) + r * FB_ROW + ch * 16,
                      Vsrc + (size_t)r * J_ + j1 + ch * 8);
            }
            int dbase = (t + 2) * 64 - s0 + 960;
            int sl = (t + 2) % 3;
#pragma unroll
            for (int it = 0; it < 4; it++) {
                int idx = it * 128 + tid;
                int r = idx >> 3, ch = idx & 7;
                int d = dbase + r;
                int ok = ((unsigned)d < (unsigned)J_) ? 16 : 0;
                int dc = d < 0 ? 0 : (d >= J_ ? J_ - 1 : d);
                cpa16z(sb + FA_PW(sl) + r * FB_ROW + ch * 16,
                       g_pph + (size_t)dc * HI_ + h * 64 + ch * 8, ok);
            }
            if (tid < 16) cpa16(sb + FA_DUK(nb) + tid * 16, Dsrc + j1 + tid * 4);
            asm volatile("cp.async.commit_group;" ::: "memory");
        }

        int cur = t & 1, j0 = t * 64;
        uint32_t pwA = sb + FA_PW(t % 3), pwB = sb + FA_PW((t + 1) % 3);
        const float* duk_s = (const float*)(smc + FA_DUK(cur));

        // ---- pos scores -> Bt ----
#pragma unroll
        for (int n = 0; n < 16; n++) {
            float ac[4] = {0.f, 0.f, 0.f, 0.f};
            uint32_t base = (n < 8) ? pwA : pwB;
            uint32_t roff = (uint32_t)(((n & 7) * 8 + b_row) * FB_ROW);
#pragma unroll
            for (int kk = 0; kk < 4; kk++) {
                uint32_t bf[2];
                ldm_x2(bf, base + roff + kk * 32 + b_hi);
                mma16816(ac, af[kk], bf);
            }
            *(float2*)&Btf[r1 * 132 + n * 8 + c0] = make_float2(ac[0], ac[1]);
            *(float2*)&Btf[(r1 + 8) * 132 + n * 8 + c0] = make_float2(ac[2], ac[3]);
        }
        __syncwarp();

        // ---- content scores ----
        float lg[8][4];
#pragma unroll
        for (int n = 0; n < 8; n++) {
            float ac[4] = {0.f, 0.f, 0.f, 0.f};
            uint32_t roff = (uint32_t)((n * 8 + b_row) * FB_ROW);
#pragma unroll
            for (int kk = 0; kk < 4; kk++) {
                uint32_t bf[2];
                ldm_x2(bf, sb + FA_K(cur) + roff + kk * 32 + b_hi);
                mma16816(ac, af[kk], bf);
            }
            lg[n][0] = ac[0]; lg[n][1] = ac[1]; lg[n][2] = ac[2]; lg[n][3] = ac[3];
        }

        // ---- combine ----
        int lim1 = P_ + s0 + r1 - j0;
        int lim2 = lim1 + 8;
        int r2 = r1 + 8;
#pragma unroll
        for (int n = 0; n < 8; n++) {
            int c = n * 8 + c0;
            float d0v = duk_s[c], d1v = duk_s[c + 1];
            float v00 = (lg[n][0] + d0v + Btf[r1 * 132 + (c - r1 + 63)]) * 0.125f;
            float v01 = (lg[n][1] + d1v + Btf[r1 * 132 + (c + 1 - r1 + 63)]) * 0.125f;
            float v10 = (lg[n][2] + d0v + Btf[r2 * 132 + (c - r2 + 63)]) * 0.125f;
            float v11 = (lg[n][3] + d1v + Btf[r2 * 132 + (c + 1 - r2 + 63)]) * 0.125f;
            lg[n][0] = (c     <= lim1) ? v00 : -1e30f;
            lg[n][1] = (c + 1 <= lim1) ? v01 : -1e30f;
            lg[n][2] = (c     <= lim2) ? v10 : -1e30f;
            lg[n][3] = (c + 1 <= lim2) ? v11 : -1e30f;
        }

        // ---- online softmax ----
        float rx1 = -1e30f, rx2 = -1e30f;
#pragma unroll
        for (int n = 0; n < 8; n++) {
            rx1 = fmaxf(rx1, fmaxf(lg[n][0], lg[n][1]));
            rx2 = fmaxf(rx2, fmaxf(lg[n][2], lg[n][3]));
        }
#pragma unroll
        for (int o = 1; o < 4; o <<= 1) {
            rx1 = fmaxf(rx1, __shfl_xor_sync(0xffffffffu, rx1, o));
            rx2 = fmaxf(rx2, __shfl_xor_sync(0xffffffffu, rx2, o));
        }
        float m1n = fmaxf(m1, rx1), m2n = fmaxf(m2, rx2);
        float sc1 = __expf(m1 - m1n), sc2 = __expf(m2 - m2n);
        m1 = m1n; m2 = m2n;
        float rs1 = 0.f, rs2 = 0.f;
#pragma unroll
        for (int n = 0; n < 8; n++) {
            lg[n][0] = __expf(lg[n][0] - m1); rs1 += lg[n][0];
            lg[n][1] = __expf(lg[n][1] - m1); rs1 += lg[n][1];
            lg[n][2] = __expf(lg[n][2] - m2); rs2 += lg[n][2];
            lg[n][3] = __expf(lg[n][3] - m2); rs2 += lg[n][3];
        }
#pragma unroll
        for (int o = 1; o < 4; o <<= 1) {
            rs1 += __shfl_xor_sync(0xffffffffu, rs1, o);
            rs2 += __shfl_xor_sync(0xffffffffu, rs2, o);
        }
        l1 = l1 * sc1 + rs1;
        l2 = l2 * sc2 + rs2;
#pragma unroll
        for (int g = 0; g < 8; g++) {
            O[g][0] *= sc1; O[g][1] *= sc1; O[g][2] *= sc2; O[g][3] *= sc2;
        }

        // ---- P @ V ----
#pragma unroll
        for (int kb = 0; kb < 4; kb++) {
            uint32_t pa[4];
            pa[0] = pkhf2(lg[2 * kb][0], lg[2 * kb][1]);
            pa[1] = pkhf2(lg[2 * kb][2], lg[2 * kb][3]);
            pa[2] = pkhf2(lg[2 * kb + 1][0], lg[2 * kb + 1][1]);
            pa[3] = pkhf2(lg[2 * kb + 1][2], lg[2 * kb + 1][3]);
#pragma unroll
            for (int n2 = 0; n2 < 8; n2++) {
                uint32_t bv[2];
                ldm_x2(bv, sb + FA_VT(cur) + (uint32_t)((n2 * 8 + b_row) * FB_ROW) + kb * 32 + b_hi);
                mma16816(O[n2], pa, bv);
            }
        }

        asm volatile("cp.async.wait_group 0;" ::: "memory");
        __syncthreads();
    }

    // ---- epilogue ----
    float inv1 = 1.f / l1, inv2 = 1.f / l2;
    __half* d1 = g_ahh + ((size_t)(s0 + r1) * B_ + b) * HI_ + h * 64;
    __half* d2 = g_ahh + ((size_t)(s0 + r1 + 8) * B_ + b) * HI_ + h * 64;
#pragma unroll
    for (int g = 0; g < 8; g++) {
        *(uint32_t*)(d1 + g * 8 + c0) = pkhf2(O[g][0] * inv1, O[g][1] * inv1);
        *(uint32_t*)(d2 + g * 8 + c0) = pkhf2(O[g][2] * inv2, O[g][3] * inv2);
    }
}

// ---------------- fp32 -> fp16 ----------------------------------------------
__global__ __launch_bounds__(256) void cvt_kernel(const float* __restrict__ x,
                                                  __half* __restrict__ o, int n) {
    int i = (blockIdx.x * 256 + threadIdx.x) * 4;
    if (i >= n) return;
    float4 v = *(const float4*)&x[i];
    *(__half2*)&o[i] = __floats2half2_rn(v.x, v.y);
    *(__half2*)&o[i + 2] = __floats2half2_rn(v.z, v.w);
}

// ---------------- duk[bh][j] = (u - v) · K_h[j,b,h,:] -----------------------
__global__ __launch_bounds__(256) void duk_kernel(const float* __restrict__ u,
                                                  const float* __restrict__ v) {
    int id = blockIdx.x * 256 + threadIdx.x;   // bh * J + j
    int bh = id >> 11, j = id & (J_ - 1);
    int b = bh >> 4, h = bh & 15;
    const __half* kp = g_kvh + ((size_t)j * B_ + b) * 2048 + h * 64;
    float s = 0.f;
#pragma unroll
    for (int i = 0; i < 64; i += 2) {
        __half2 k2 = *(const __half2*)&kp[i];
        float2 kf = __half22float2(k2);
        s += (u[h * 64 + i] - v[h * 64 + i]) * kf.x;
        s += (u[h * 64 + i + 1] - v[h * 64 + i + 1]) * kf.y;
    }
    g_duk[id] = s;
}

// ---------------- W[K,N] -> T[N,K] transpose + fp16 -------------------------
__global__ void ttrans_kernel(const float* __restrict__ W,
                              __half* __restrict__ T, int Kd, int Nd) {
    __shared__ float t[32][33];
    int n0 = blockIdx.x * 32, k0 = blockIdx.y * 32;
    int tx = threadIdx.x, ty = threadIdx.y;
#pragma unroll
    for (int r = 0; r < 32; r += 8)
        t[ty + r][tx] = W[(size_t)(k0 + ty + r) * Nd + n0 + tx];
    __syncthreads();
#pragma unroll
    for (int r = 0; r < 32; r += 8)
        T[(size_t)(n0 + ty + r) * Kd + k0 + tx] = __float2half(t[tx][ty + r]);
}

// ---------------- values(fp16) -> V^T fp16 per (b,h): [i][j] ----------------
__global__ void vt_kernel() {
    __shared__ float t[32][33];
    int j0 = blockIdx.x * 32, i0 = blockIdx.y * 32;
    int bh = blockIdx.z;
    int b = bh >> 4, h = bh & 15;
    int tx = threadIdx.x, ty = threadIdx.y;
#pragma unroll
    for (int r = 0; r < 32; r += 8)
        t[ty + r][tx] = __half2float(
            g_kvh[((size_t)(j0 + ty + r) * B_ + b) * 2048 + 1024 + h * 64 + i0 + tx]);
    __syncthreads();
#pragma unroll
    for (int r = 0; r < 32; r += 8)
        g_vth[((size_t)bh * 64 + i0 + ty + r) * J_ + j0 + tx] =
            __float2half(t[tx][ty + r]);
}

// ---------------- LayerNorm over E=1024 ------------------------------------
__global__ __launch_bounds__(256) void ln_kernel(const float* __restrict__ gamma,
                                                 const float* __restrict__ beta,
                                                 float* __restrict__ out) {
    int row = blockIdx.x;
    const float* x = g_o + (size_t)row * E_;
    int tid = threadIdx.x;
    float4 v = *(const float4*)&x[tid << 2];
    float s1 = v.x + v.y + v.z + v.w;
    float s2 = v.x * v.x + v.y * v.y + v.z * v.z + v.w * v.w;
    __shared__ float r1[8], r2[8];
#pragma unroll
    for (int o = 16; o > 0; o >>= 1) {
        s1 += __shfl_xor_sync(0xffffffffu, s1, o);
        s2 += __shfl_xor_sync(0xffffffffu, s2, o);
    }
    if ((tid & 31) == 0) { r1[tid >> 5] = s1; r2[tid >> 5] = s2; }
    __syncthreads();
    float S1 = 0.f, S2 = 0.f;
#pragma unroll
    for (int i = 0; i < 8; i++) { S1 += r1[i]; S2 += r2[i]; }
    float mean = S1 * (1.0f / E_);
    float var = S2 * (1.0f / E_) - mean * mean;
    float rstd = rsqrtf(var + 1e-5f);
    float4 g = *(const float4*)&gamma[tid << 2];
    float4 bb = *(const float4*)&beta[tid << 2];
    float4 o;
    o.x = (v.x - mean) * rstd * g.x + bb.x;
    o.y = (v.y - mean) * rstd * g.y + bb.y;
    o.z = (v.z - mean) * rstd * g.z + bb.z;
    o.w = (v.w - mean) * rstd * g.w + bb.w;
    *(float4*)&out[(size_t)row * E_ + (tid << 2)] = o;
}

// ---------------- launch ----------------------------------------------------
extern "C" void kernel_launch(void* const* d_in, const int* in_sizes, int n_in,
                              void* d_out, int out_size) {
    (void)in_sizes; (void)n_in; (void)out_size;
    const float* inputMHA = (const float*)d_in[0];
    const float* posEmb   = (const float*)d_in[1];
    const float* memory   = (const float*)d_in[2];
    const float* u        = (const float*)d_in[3];
    const float* v        = (const float*)d_in[4];
    const float* W_kv     = (const float*)d_in[6];
    const float* W_q      = (const float*)d_in[7];
    const float* W_p      = (const float*)d_in[8];
    const float* W_o      = (const float*)d_in[9];
    const float* gamma    = (const float*)d_in[10];
    const float* beta     = (const float*)d_in[11];

    float* po;
    cudaGetSymbolAddress((void**)&po, g_o);
    __half *xh, *peh, *ahh, *qvh, *kvh, *pph;
    __half *wqh, *wkvh, *wph, *woh;
    cudaGetSymbolAddress((void**)&xh, g_xh);
    cudaGetSymbolAddress((void**)&peh, g_peh);
    cudaGetSymbolAddress((void**)&ahh, g_ahh);
    cudaGetSymbolAddress((void**)&qvh, g_qvh);
    cudaGetSymbolAddress((void**)&kvh, g_kvh);
    cudaGetSymbolAddress((void**)&pph, g_pph);
    cudaGetSymbolAddress((void**)&wqh, g_wqh);
    cudaGetSymbolAddress((void**)&wkvh, g_wkvh);
    cudaGetSymbolAddress((void**)&wph, g_wph);
    cudaGetSymbolAddress((void**)&woh, g_woh);

    cudaFuncSetAttribute(hmma_gemm, cudaFuncAttributeMaxDynamicSharedMemorySize, GM_SMEM);
    cudaFuncSetAttribute(fused_attn, cudaFuncAttributeMaxDynamicSharedMemorySize, FA_SMEM);

    // ---- convert inputs to fp16 ----
    cvt_kernel<<<4096, 256>>>(memory, xh, P_ * B_ * E_);
    cvt_kernel<<<4096, 256>>>(inputMHA, xh + (size_t)P_ * B_ * E_, S_ * B_ * E_);
    cvt_kernel<<<2048, 256>>>(posEmb, peh, J_ * E_);
    ttrans_kernel<<<dim3(HI_ / 32, E_ / 32), dim3(32, 8)>>>(W_q, wqh, E_, HI_);
    ttrans_kernel<<<dim3(2 * HI_ / 32, E_ / 32), dim3(32, 8)>>>(W_kv, wkvh, E_, 2 * HI_);
    ttrans_kernel<<<dim3(HI_ / 32, E_ / 32), dim3(32, 8)>>>(W_p, wph, E_, HI_);
    ttrans_kernel<<<dim3(E_ / 32, HI_ / 32), dim3(32, 8)>>>(W_o, woh, HI_, E_);

    // ---- linears (HMMA fp16 x1, fused fp16 epilogues) ----
    hmma_gemm<<<dim3(HI_ / 128, (S_ * B_) / 128), 256, GM_SMEM>>>(
        xh + (size_t)P_ * B_ * E_, wqh, nullptr, nullptr, qvh, v, S_ * B_, HI_, E_);
    hmma_gemm<<<dim3(2 * HI_ / 128, (J_ * B_) / 128), 256, GM_SMEM>>>(
        xh, wkvh, nullptr, nullptr, kvh, nullptr, J_ * B_, 2 * HI_, E_);
    hmma_gemm<<<dim3(HI_ / 128, J_ / 128), 256, GM_SMEM>>>(
        peh, wph, nullptr, nullptr, pph, nullptr, J_, HI_, E_);

    // ---- operand prep for fused attention ----
    vt_kernel<<<dim3(J_ / 32, 2, B_ * H_), dim3(32, 8)>>>();
    duk_kernel<<<(B_ * H_ * J_) / 256, 256>>>(u, v);

    // ---- fused attention (scores + softmax + P@V) -> g_ahh ----
    fused_attn<<<dim3(S_ / 64, B_ * H_), 128, FA_SMEM>>>();

    // ---- output projection + residual ----
    hmma_gemm<<<dim3(E_ / 128, (S_ * B_) / 128), 256, GM_SMEM>>>(
        ahh, woh, inputMHA, po, nullptr, nullptr, S_ * B_, E_, HI_);

    // ---- LayerNorm ----
    ln_kernel<<<S_ * B_, 256>>>(gamma, beta, (float*)d_out);
}